// round 10
// baseline (speedup 1.0000x reference)
#include <cuda_runtime.h>
#include <cuda_bf16.h>
#include <cstdint>

// ConvGRU cell via warp-level mma.sync (HMMA bf16, f32 accum), compute_103-safe.
// fp32 accuracy via bf16 hi/lo split (3 terms: Ah*Wh + Al*Wh + Ah*Wl).
// R10: A-fragment reuse across matrices (wxz/wxr/wc share xs frags, whz/whr
// share hs frags), uint4-packed B fragments (1 LDS.128 per (m,kt,nt)), and
// no f32 staging -- h_t / y stores go through the bf16-split ts tile.
//
// Block = 128 threads = 4 warps; warp w owns pixels [32w,32w+32): tiles are
// warp-local, only __syncwarp in the pipeline.

#define HW 65536        // 256*256
#define NB 8

// smem: wf 28672 B | xs 18432 | hs 18432 | ts 18432  = 83968 B
#define WF_BYTES   28672
#define TILE_BYTES 18432
#define SMEM_TOTAL (WF_BYTES + 3 * TILE_BYTES)

__device__ __align__(16) uint32_t g_wfrag[7168];
__device__ float g_bias_stage[128];
__constant__ float cBias[128];   // [bz | br | bc | by]

__device__ __forceinline__ float sigmoidf_(float a) {
    a = fminf(fmaxf(a, -30.f), 30.f);
    float e = __expf(-a);
    return __fdividef(1.f, 1.f + e);
}
__device__ __forceinline__ float tanhf_(float a) {
    a = fminf(fmaxf(a, -15.f), 15.f);
    float e = __expf(-2.f * a);
    return (1.f - e) * __fdividef(1.f, 1.f + e);
}
__device__ __forceinline__ void split2(float a, float b, uint32_t& hi, uint32_t& lo) {
    __nv_bfloat16 ha = __float2bfloat16(a);
    __nv_bfloat16 hb = __float2bfloat16(b);
    __nv_bfloat16 la = __float2bfloat16(a - __bfloat162float(ha));
    __nv_bfloat16 lb = __float2bfloat16(b - __bfloat162float(hb));
    hi = (uint32_t)__bfloat16_as_ushort(ha) | ((uint32_t)__bfloat16_as_ushort(hb) << 16);
    lo = (uint32_t)__bfloat16_as_ushort(la) | ((uint32_t)__bfloat16_as_ushort(lb) << 16);
}
__device__ __forceinline__ float bf_lo(uint32_t v) {
    return __bfloat162float(__ushort_as_bfloat16((unsigned short)(v & 0xFFFF)));
}
__device__ __forceinline__ float bf_hi(uint32_t v) {
    return __bfloat162float(__ushort_as_bfloat16((unsigned short)(v >> 16)));
}
__device__ __forceinline__ uint32_t smem_u32(const void* p) {
    uint32_t a;
    asm("{ .reg .u64 t; cvta.to.shared.u64 t, %1; cvt.u32.u64 %0, t; }"
        : "=r"(a) : "l"(p));
    return a;
}
__device__ __forceinline__ void ldmA(uint32_t a[4], uint32_t addr) {
    asm volatile("ldmatrix.sync.aligned.m8n8.x4.shared.b16 {%0,%1,%2,%3}, [%4];"
                 : "=r"(a[0]), "=r"(a[1]), "=r"(a[2]), "=r"(a[3]) : "r"(addr));
}
__device__ __forceinline__ void mma16816(float d[4], const uint32_t a[4],
                                         uint32_t b0, uint32_t b1) {
    asm volatile(
        "mma.sync.aligned.m16n8k16.row.col.f32.bf16.bf16.f32 "
        "{%0,%1,%2,%3}, {%4,%5,%6,%7}, {%8,%9}, {%0,%1,%2,%3};"
        : "+f"(d[0]), "+f"(d[1]), "+f"(d[2]), "+f"(d[3])
        : "r"(a[0]), "r"(a[1]), "r"(a[2]), "r"(a[3]), "r"(b0), "r"(b1));
}
// 3-term split MMA group: d[mt][nt] += Ah*Bh + Al*Bh + Ah*Bl
__device__ __forceinline__ void mma6(float d0[4], float d1[4],
                                     const uint32_t ah0[4], const uint32_t ah1[4],
                                     const uint32_t al0[4], const uint32_t al1[4],
                                     uint4 b) {
    mma16816(d0, ah0, b.x, b.y);
    mma16816(d1, ah1, b.x, b.y);
    mma16816(d0, al0, b.x, b.y);
    mma16816(d1, al1, b.x, b.y);
    mma16816(d0, ah0, b.z, b.w);
    mma16816(d1, ah1, b.z, b.w);
}

// prep: B fragments packed uint4 {bh0,bh1,bl0,bl1} per (m,kt,nt,lane).
__global__ void prep_kernel(
    const float* __restrict__ w_xz, const float* __restrict__ w_hz,
    const float* __restrict__ w_xr, const float* __restrict__ w_hr,
    const float* __restrict__ w_c,  const float* __restrict__ w_u,
    const float* __restrict__ w_o,
    const float* __restrict__ b_xz, const float* __restrict__ b_hz,
    const float* __restrict__ b_xr, const float* __restrict__ b_hr,
    const float* __restrict__ b_c,  const float* __restrict__ b_u,
    const float* __restrict__ b_o)
{
    int m = blockIdx.x;                  // 0..6
    int t = threadIdx.x;                 // 0..1023
    int lane = t & 31;
    int reg  = (t >> 5) & 1;
    int nt   = (t >> 6) & 3;
    int kt   = (t >> 8) & 1;
    int term = (t >> 9) & 1;
    int g = lane >> 2, tig = lane & 3;
    const float* Wm = (m == 0) ? w_xz : (m == 1) ? w_hz : (m == 2) ? w_xr :
                      (m == 3) ? w_hr : (m == 4) ? w_c  : (m == 5) ? w_u : w_o;
    int n  = nt * 8 + g;
    int kk = kt * 16 + 2 * tig + reg * 8;
    float w0 = Wm[n * 32 + kk];
    float w1 = Wm[n * 32 + kk + 1];
    __nv_bfloat16 h0 = __float2bfloat16(w0);
    __nv_bfloat16 h1 = __float2bfloat16(w1);
    uint32_t val;
    if (term == 0) {
        val = (uint32_t)__bfloat16_as_ushort(h0) |
              ((uint32_t)__bfloat16_as_ushort(h1) << 16);
    } else {
        __nv_bfloat16 l0 = __float2bfloat16(w0 - __bfloat162float(h0));
        __nv_bfloat16 l1 = __float2bfloat16(w1 - __bfloat162float(h1));
        val = (uint32_t)__bfloat16_as_ushort(l0) |
              ((uint32_t)__bfloat16_as_ushort(l1) << 16);
    }
    // uint4-friendly: [(m*2+kt)*4+nt][lane] -> 4 words {bh0,bh1,bl0,bl1}
    g_wfrag[((((m * 2 + kt) * 4 + nt) * 32) + lane) * 4 + term * 2 + reg] = val;
    if (m == 0 && t < 32) {
        g_bias_stage[ 0 + t] = b_xz[t] + b_hz[t];
        g_bias_stage[32 + t] = b_xr[t] + b_hr[t];
        g_bias_stage[64 + t] = b_c[t]  + b_u[t];
        g_bias_stage[96 + t] = b_o[t];
    }
}

__global__ void __launch_bounds__(128) gru_mma_kernel(
    const float* __restrict__ x, const float* __restrict__ h,
    float* __restrict__ out)
{
    extern __shared__ __align__(16) unsigned char dsm[];
    const uint4* wfv = (const uint4*)dsm;
    uint32_t* xs = (uint32_t*)(dsm + WF_BYTES);               // 36 u32 / row
    uint32_t* hs = (uint32_t*)(dsm + WF_BYTES + TILE_BYTES);
    uint32_t* ts = (uint32_t*)(dsm + WF_BYTES + 2 * TILE_BYTES);

    const int tid = threadIdx.x;
    const int wid = tid >> 5, lane = tid & 31;
    const int g = lane >> 2, tig = lane & 3;
    const int wpx = wid * 32;
    const int l15 = lane & 15, lhi = lane >> 4;

    const uint32_t xs_a = smem_u32(xs);
    const uint32_t hs_a = smem_u32(hs);
    const uint32_t ts_a = smem_u32(ts);

    // ---- copy B fragments (1792 uint4, coalesced) ----
    {
        const uint4* src = (const uint4*)g_wfrag;
        uint4* dst = (uint4*)dsm;
#pragma unroll
        for (int k = 0; k < 14; k++) dst[tid + k * 128] = src[tid + k * 128];
    }

    const int gp0 = blockIdx.x * 128;   // 4096 blocks cover 524288 px
    const int b   = gp0 >> 16;
    const int p0  = gp0 & 65535;
    const float* xb = x + (b * 32) * HW + p0 + tid;
    const float* hb = h + (b * 32) * HW + p0 + tid;

    // ---- load x,h (coalesced), split, fill tiles (row = own pixel) ----
#pragma unroll
    for (int j = 0; j < 16; j++) {
        float a0 = xb[(2 * j) * HW], a1 = xb[(2 * j + 1) * HW];
        float c0 = hb[(2 * j) * HW], c1 = hb[(2 * j + 1) * HW];
        uint32_t phi, plo;
        split2(a0, a1, phi, plo);
        xs[tid * 36 + j] = phi;  xs[tid * 36 + 16 + j] = plo;
        split2(c0, c1, phi, plo);
        hs[tid * 36 + j] = phi;  hs[tid * 36 + 16 + j] = plo;
    }
    __syncthreads();   // wf visible; tiles are warp-local

    // A-fragment load for one tile at (kt): ah/al for both 16-row halves
#define LDFRAGS(base_a, ah, al, kt)                                            \
    {                                                                          \
        uint32_t ca = (uint32_t)(((kt) * 16 + lhi * 8) * 2);                   \
        _Pragma("unroll")                                                      \
        for (int mt = 0; mt < 2; mt++) {                                       \
            uint32_t rowb = (base_a) + (uint32_t)((wpx + mt * 16 + l15) * 144);\
            ldmA((ah)[mt], rowb + ca);                                         \
            ldmA((al)[mt], rowb + ca + 64);                                    \
        }                                                                      \
    }

#define BFRAG(m, kt, nt) wfv[(((m) * 2 + (kt)) * 4 + (nt)) * 32 + lane]

    // ---- phase 1: z_pre, r_pre, and the Wc*x part of the candidate ----
    float dz[2][4][4] = {}, dr[2][4][4] = {}, dc[2][4][4] = {};
#pragma unroll
    for (int kt = 0; kt < 2; kt++) {
        uint32_t ah[2][4], al[2][4];
        LDFRAGS(xs_a, ah, al, kt)
#pragma unroll
        for (int nt = 0; nt < 4; nt++) {
            mma6(dz[0][nt], dz[1][nt], ah[0], ah[1], al[0], al[1], BFRAG(0, kt, nt));
            mma6(dr[0][nt], dr[1][nt], ah[0], ah[1], al[0], al[1], BFRAG(2, kt, nt));
            mma6(dc[0][nt], dc[1][nt], ah[0], ah[1], al[0], al[1], BFRAG(4, kt, nt));
        }
        LDFRAGS(hs_a, ah, al, kt)
#pragma unroll
        for (int nt = 0; nt < 4; nt++) {
            mma6(dz[0][nt], dz[1][nt], ah[0], ah[1], al[0], al[1], BFRAG(1, kt, nt));
            mma6(dr[0][nt], dr[1][nt], ah[0], ah[1], al[0], al[1], BFRAG(3, kt, nt));
        }
    }

    // z = sigmoid(z_pre + bz) kept in dz; rv = sigmoid(r_pre + br) * h -> ts
#pragma unroll
    for (int mt = 0; mt < 2; mt++)
#pragma unroll
        for (int nt = 0; nt < 4; nt++) {
            const int ch0 = nt * 8 + 2 * tig;
            const float bz0 = cBias[ch0], bz1 = cBias[ch0 + 1];
            const float br0 = cBias[32 + ch0], br1 = cBias[32 + ch0 + 1];
#pragma unroll
            for (int hf = 0; hf < 2; hf++) {
                int px = wpx + mt * 16 + g + hf * 8;
                int wb = px * 36 + nt * 4 + tig;
                uint32_t hh = hs[wb], hl = hs[wb + 16];
                float h0 = bf_lo(hh) + bf_lo(hl);
                float h1 = bf_hi(hh) + bf_hi(hl);
                dz[mt][nt][hf * 2 + 0] = sigmoidf_(dz[mt][nt][hf * 2 + 0] + bz0);
                dz[mt][nt][hf * 2 + 1] = sigmoidf_(dz[mt][nt][hf * 2 + 1] + bz1);
                float r0 = sigmoidf_(dr[mt][nt][hf * 2 + 0] + br0) * h0;
                float r1 = sigmoidf_(dr[mt][nt][hf * 2 + 1] + br1) * h1;
                uint32_t phi, plo;
                split2(r0, r1, phi, plo);
                ts[wb] = phi;  ts[wb + 16] = plo;
            }
        }
    __syncwarp();

    // ---- phase 2: dc += Wu * rv ----
#pragma unroll
    for (int kt = 0; kt < 2; kt++) {
        uint32_t ah[2][4], al[2][4];
        LDFRAGS(ts_a, ah, al, kt)
#pragma unroll
        for (int nt = 0; nt < 4; nt++)
            mma6(dc[0][nt], dc[1][nt], ah[0], ah[1], al[0], al[1], BFRAG(5, kt, nt));
    }
    __syncwarp();   // all ts (rv) ldmatrix reads done before overwrite

    // blend: h_t = h + z*(tanh(c_pre+bc) - h) -> ts (bf16 split)
#pragma unroll
    for (int mt = 0; mt < 2; mt++)
#pragma unroll
        for (int nt = 0; nt < 4; nt++) {
            const int ch0 = nt * 8 + 2 * tig;
            const float bc0 = cBias[64 + ch0], bc1 = cBias[64 + ch0 + 1];
#pragma unroll
            for (int hf = 0; hf < 2; hf++) {
                int px = wpx + mt * 16 + g + hf * 8;
                int wb = px * 36 + nt * 4 + tig;
                uint32_t hh = hs[wb], hl = hs[wb + 16];
                float h0 = bf_lo(hh) + bf_lo(hl);
                float h1 = bf_hi(hh) + bf_hi(hl);
                float c0 = tanhf_(dc[mt][nt][hf * 2 + 0] + bc0);
                float c1 = tanhf_(dc[mt][nt][hf * 2 + 1] + bc1);
                float t0 = fmaf(dz[mt][nt][hf * 2 + 0], c0 - h0, h0);
                float t1 = fmaf(dz[mt][nt][hf * 2 + 1], c1 - h1, h1);
                uint32_t phi, plo;
                split2(t0, t1, phi, plo);
                ts[wb] = phi;  ts[wb + 16] = plo;
            }
        }
    __syncwarp();

    // coalesced h_t store: thread reads its own pixel row from ts
    {
        float* houtb = out + NB * 32 * HW + (b * 32) * HW + p0 + tid;
#pragma unroll
        for (int w = 0; w < 16; w++) {
            int ch0 = (w >> 2) * 8 + 2 * (w & 3);
            uint32_t hh = ts[tid * 36 + w], hl = ts[tid * 36 + 16 + w];
            houtb[ch0 * HW]       = bf_lo(hh) + bf_lo(hl);
            houtb[(ch0 + 1) * HW] = bf_hi(hh) + bf_hi(hl);
        }
    }

    // ---- phase 3: y = Wo * h_t + by ----
    float dy[2][4][4] = {};
#pragma unroll
    for (int kt = 0; kt < 2; kt++) {
        uint32_t ah[2][4], al[2][4];
        LDFRAGS(ts_a, ah, al, kt)
#pragma unroll
        for (int nt = 0; nt < 4; nt++)
            mma6(dy[0][nt], dy[1][nt], ah[0], ah[1], al[0], al[1], BFRAG(6, kt, nt));
    }
    __syncwarp();   // ts (ht) reads done before y-split overwrite

    // y + bias -> ts (bf16 split), then coalesced row store
#pragma unroll
    for (int mt = 0; mt < 2; mt++)
#pragma unroll
        for (int nt = 0; nt < 4; nt++) {
            const int ch0 = nt * 8 + 2 * tig;
            const float by0 = cBias[96 + ch0], by1 = cBias[96 + ch0 + 1];
#pragma unroll
            for (int hf = 0; hf < 2; hf++) {
                int px = wpx + mt * 16 + g + hf * 8;
                int wb = px * 36 + nt * 4 + tig;
                uint32_t phi, plo;
                split2(dy[mt][nt][hf * 2 + 0] + by0,
                       dy[mt][nt][hf * 2 + 1] + by1, phi, plo);
                ts[wb] = phi;  ts[wb + 16] = plo;
            }
        }
    __syncwarp();

    {
        float* youtb = out + (b * 32) * HW + p0 + tid;
#pragma unroll
        for (int w = 0; w < 16; w++) {
            int ch0 = (w >> 2) * 8 + 2 * (w & 3);
            uint32_t yh = ts[tid * 36 + w], yl = ts[tid * 36 + 16 + w];
            youtb[ch0 * HW]       = bf_lo(yh) + bf_lo(yl);
            youtb[(ch0 + 1) * HW] = bf_hi(yh) + bf_hi(yl);
        }
    }
}

extern "C" void kernel_launch(void* const* d_in, const int* in_sizes, int n_in,
                              void* d_out, int out_size) {
    const float* x    = (const float*)d_in[0];
    const float* h    = (const float*)d_in[1];
    const float* w_xz = (const float*)d_in[2];
    const float* b_xz = (const float*)d_in[3];
    const float* w_hz = (const float*)d_in[4];
    const float* b_hz = (const float*)d_in[5];
    const float* w_xr = (const float*)d_in[6];
    const float* b_xr = (const float*)d_in[7];
    const float* w_hr = (const float*)d_in[8];
    const float* b_hr = (const float*)d_in[9];
    const float* w_c  = (const float*)d_in[10];
    const float* b_c  = (const float*)d_in[11];
    const float* w_u  = (const float*)d_in[12];
    const float* b_u  = (const float*)d_in[13];
    const float* w_o  = (const float*)d_in[14];
    const float* b_o  = (const float*)d_in[15];
    float* out = (float*)d_out;

    prep_kernel<<<7, 1024>>>(w_xz, w_hz, w_xr, w_hr, w_c, w_u, w_o,
                             b_xz, b_hz, b_xr, b_hr, b_c, b_u, b_o);

    void *csym = nullptr, *gsym = nullptr;
    cudaGetSymbolAddress(&csym, cBias);
    cudaGetSymbolAddress(&gsym, g_bias_stage);
    cudaMemcpyAsync(csym, gsym, sizeof(float) * 128, cudaMemcpyDeviceToDevice);

    cudaFuncSetAttribute(gru_mma_kernel,
                         cudaFuncAttributeMaxDynamicSharedMemorySize, SMEM_TOTAL);
    gru_mma_kernel<<<4096, 128, SMEM_TOTAL>>>(x, h, out);
}

// round 11
// speedup vs baseline: 1.2782x; 1.2782x over previous
#include <cuda_runtime.h>
#include <cuda_bf16.h>
#include <cstdint>

// ConvGRU cell via warp-level mma.sync (HMMA bf16, f32 accum), compute_103-safe.
// fp32 accuracy via bf16 hi/lo split (3 terms: Ah*Wh + Al*Wh + Ah*Wl).
// R11: two tiles instead of three -- xs is dead after phase 1, so rv / h_t / y
// reuse it in place. smem 84KB -> 64KB per CTA => 3 CTAs / 12 warps per SM
// (R10 profile showed a latency-bound kernel at 8 warps/SM, all pipes <=35%).
//
// Block = 128 threads = 4 warps; warp w owns pixels [32w,32w+32): tiles are
// warp-local, only __syncwarp in the pipeline.

#define HW 65536        // 256*256
#define NB 8

// smem: wf 28672 B | xs 18432 | hs 18432  = 65536 B
#define WF_BYTES   28672
#define TILE_BYTES 18432
#define SMEM_TOTAL (WF_BYTES + 2 * TILE_BYTES)

__device__ __align__(16) uint32_t g_wfrag[7168];
__device__ float g_bias_stage[128];
__constant__ float cBias[128];   // [bz | br | bc | by]

__device__ __forceinline__ float sigmoidf_(float a) {
    a = fminf(fmaxf(a, -30.f), 30.f);
    float e = __expf(-a);
    return __fdividef(1.f, 1.f + e);
}
__device__ __forceinline__ float tanhf_(float a) {
    a = fminf(fmaxf(a, -15.f), 15.f);
    float e = __expf(-2.f * a);
    return (1.f - e) * __fdividef(1.f, 1.f + e);
}
__device__ __forceinline__ void split2(float a, float b, uint32_t& hi, uint32_t& lo) {
    __nv_bfloat16 ha = __float2bfloat16(a);
    __nv_bfloat16 hb = __float2bfloat16(b);
    __nv_bfloat16 la = __float2bfloat16(a - __bfloat162float(ha));
    __nv_bfloat16 lb = __float2bfloat16(b - __bfloat162float(hb));
    hi = (uint32_t)__bfloat16_as_ushort(ha) | ((uint32_t)__bfloat16_as_ushort(hb) << 16);
    lo = (uint32_t)__bfloat16_as_ushort(la) | ((uint32_t)__bfloat16_as_ushort(lb) << 16);
}
__device__ __forceinline__ float bf_lo(uint32_t v) {
    return __bfloat162float(__ushort_as_bfloat16((unsigned short)(v & 0xFFFF)));
}
__device__ __forceinline__ float bf_hi(uint32_t v) {
    return __bfloat162float(__ushort_as_bfloat16((unsigned short)(v >> 16)));
}
__device__ __forceinline__ uint32_t smem_u32(const void* p) {
    uint32_t a;
    asm("{ .reg .u64 t; cvta.to.shared.u64 t, %1; cvt.u32.u64 %0, t; }"
        : "=r"(a) : "l"(p));
    return a;
}
__device__ __forceinline__ void ldmA(uint32_t a[4], uint32_t addr) {
    asm volatile("ldmatrix.sync.aligned.m8n8.x4.shared.b16 {%0,%1,%2,%3}, [%4];"
                 : "=r"(a[0]), "=r"(a[1]), "=r"(a[2]), "=r"(a[3]) : "r"(addr));
}
__device__ __forceinline__ void mma16816(float d[4], const uint32_t a[4],
                                         uint32_t b0, uint32_t b1) {
    asm volatile(
        "mma.sync.aligned.m16n8k16.row.col.f32.bf16.bf16.f32 "
        "{%0,%1,%2,%3}, {%4,%5,%6,%7}, {%8,%9}, {%0,%1,%2,%3};"
        : "+f"(d[0]), "+f"(d[1]), "+f"(d[2]), "+f"(d[3])
        : "r"(a[0]), "r"(a[1]), "r"(a[2]), "r"(a[3]), "r"(b0), "r"(b1));
}
// 3-term split MMA group: d[mt][nt] += Ah*Bh + Al*Bh + Ah*Bl
__device__ __forceinline__ void mma6(float d0[4], float d1[4],
                                     const uint32_t ah0[4], const uint32_t ah1[4],
                                     const uint32_t al0[4], const uint32_t al1[4],
                                     uint4 b) {
    mma16816(d0, ah0, b.x, b.y);
    mma16816(d1, ah1, b.x, b.y);
    mma16816(d0, al0, b.x, b.y);
    mma16816(d1, al1, b.x, b.y);
    mma16816(d0, ah0, b.z, b.w);
    mma16816(d1, ah1, b.z, b.w);
}

// prep: B fragments packed uint4 {bh0,bh1,bl0,bl1} per (m,kt,nt,lane).
__global__ void prep_kernel(
    const float* __restrict__ w_xz, const float* __restrict__ w_hz,
    const float* __restrict__ w_xr, const float* __restrict__ w_hr,
    const float* __restrict__ w_c,  const float* __restrict__ w_u,
    const float* __restrict__ w_o,
    const float* __restrict__ b_xz, const float* __restrict__ b_hz,
    const float* __restrict__ b_xr, const float* __restrict__ b_hr,
    const float* __restrict__ b_c,  const float* __restrict__ b_u,
    const float* __restrict__ b_o)
{
    int m = blockIdx.x;                  // 0..6
    int t = threadIdx.x;                 // 0..1023
    int lane = t & 31;
    int reg  = (t >> 5) & 1;
    int nt   = (t >> 6) & 3;
    int kt   = (t >> 8) & 1;
    int term = (t >> 9) & 1;
    int g = lane >> 2, tig = lane & 3;
    const float* Wm = (m == 0) ? w_xz : (m == 1) ? w_hz : (m == 2) ? w_xr :
                      (m == 3) ? w_hr : (m == 4) ? w_c  : (m == 5) ? w_u : w_o;
    int n  = nt * 8 + g;
    int kk = kt * 16 + 2 * tig + reg * 8;
    float w0 = Wm[n * 32 + kk];
    float w1 = Wm[n * 32 + kk + 1];
    __nv_bfloat16 h0 = __float2bfloat16(w0);
    __nv_bfloat16 h1 = __float2bfloat16(w1);
    uint32_t val;
    if (term == 0) {
        val = (uint32_t)__bfloat16_as_ushort(h0) |
              ((uint32_t)__bfloat16_as_ushort(h1) << 16);
    } else {
        __nv_bfloat16 l0 = __float2bfloat16(w0 - __bfloat162float(h0));
        __nv_bfloat16 l1 = __float2bfloat16(w1 - __bfloat162float(h1));
        val = (uint32_t)__bfloat16_as_ushort(l0) |
              ((uint32_t)__bfloat16_as_ushort(l1) << 16);
    }
    // uint4: [(m*2+kt)*4+nt][lane] -> {bh0,bh1,bl0,bl1}
    g_wfrag[((((m * 2 + kt) * 4 + nt) * 32) + lane) * 4 + term * 2 + reg] = val;
    if (m == 0 && t < 32) {
        g_bias_stage[ 0 + t] = b_xz[t] + b_hz[t];
        g_bias_stage[32 + t] = b_xr[t] + b_hr[t];
        g_bias_stage[64 + t] = b_c[t]  + b_u[t];
        g_bias_stage[96 + t] = b_o[t];
    }
}

__global__ void __launch_bounds__(128) gru_mma_kernel(
    const float* __restrict__ x, const float* __restrict__ h,
    float* __restrict__ out)
{
    extern __shared__ __align__(16) unsigned char dsm[];
    const uint4* wfv = (const uint4*)dsm;
    uint32_t* xs = (uint32_t*)(dsm + WF_BYTES);               // 36 u32 / row
    uint32_t* hs = (uint32_t*)(dsm + WF_BYTES + TILE_BYTES);

    const int tid = threadIdx.x;
    const int wid = tid >> 5, lane = tid & 31;
    const int g = lane >> 2, tig = lane & 3;
    const int wpx = wid * 32;
    const int l15 = lane & 15, lhi = lane >> 4;

    const uint32_t xs_a = smem_u32(xs);
    const uint32_t hs_a = smem_u32(hs);

    // ---- copy B fragments (1792 uint4, coalesced) ----
    {
        const uint4* src = (const uint4*)g_wfrag;
        uint4* dst = (uint4*)dsm;
#pragma unroll
        for (int k = 0; k < 14; k++) dst[tid + k * 128] = src[tid + k * 128];
    }

    const int gp0 = blockIdx.x * 128;   // 4096 blocks cover 524288 px
    const int b   = gp0 >> 16;
    const int p0  = gp0 & 65535;
    const float* xb = x + (b * 32) * HW + p0 + tid;
    const float* hb = h + (b * 32) * HW + p0 + tid;

    // ---- load x,h (coalesced), split, fill tiles (row = own pixel) ----
#pragma unroll
    for (int j = 0; j < 16; j++) {
        float a0 = xb[(2 * j) * HW], a1 = xb[(2 * j + 1) * HW];
        float c0 = hb[(2 * j) * HW], c1 = hb[(2 * j + 1) * HW];
        uint32_t phi, plo;
        split2(a0, a1, phi, plo);
        xs[tid * 36 + j] = phi;  xs[tid * 36 + 16 + j] = plo;
        split2(c0, c1, phi, plo);
        hs[tid * 36 + j] = phi;  hs[tid * 36 + 16 + j] = plo;
    }
    __syncthreads();   // wf visible; tiles are warp-local

#define LDFRAGS(base_a, ah, al, kt)                                            \
    {                                                                          \
        uint32_t ca = (uint32_t)(((kt) * 16 + lhi * 8) * 2);                   \
        _Pragma("unroll")                                                      \
        for (int mt = 0; mt < 2; mt++) {                                       \
            uint32_t rowb = (base_a) + (uint32_t)((wpx + mt * 16 + l15) * 144);\
            ldmA((ah)[mt], rowb + ca);                                         \
            ldmA((al)[mt], rowb + ca + 64);                                    \
        }                                                                      \
    }

#define BFRAG(m, kt, nt) wfv[(((m) * 2 + (kt)) * 4 + (nt)) * 32 + lane]

    // ---- phase 1: z_pre, r_pre, and the Wc*x part of the candidate ----
    float dz[2][4][4] = {}, dr[2][4][4] = {}, dc[2][4][4] = {};
#pragma unroll
    for (int kt = 0; kt < 2; kt++) {
        uint32_t ah[2][4], al[2][4];
        LDFRAGS(xs_a, ah, al, kt)
#pragma unroll
        for (int nt = 0; nt < 4; nt++) {
            mma6(dz[0][nt], dz[1][nt], ah[0], ah[1], al[0], al[1], BFRAG(0, kt, nt));
            mma6(dr[0][nt], dr[1][nt], ah[0], ah[1], al[0], al[1], BFRAG(2, kt, nt));
            mma6(dc[0][nt], dc[1][nt], ah[0], ah[1], al[0], al[1], BFRAG(4, kt, nt));
        }
        LDFRAGS(hs_a, ah, al, kt)
#pragma unroll
        for (int nt = 0; nt < 4; nt++) {
            mma6(dz[0][nt], dz[1][nt], ah[0], ah[1], al[0], al[1], BFRAG(1, kt, nt));
            mma6(dr[0][nt], dr[1][nt], ah[0], ah[1], al[0], al[1], BFRAG(3, kt, nt));
        }
    }
    __syncwarp();   // all xs ldmatrix reads done -> xs reusable

    // z = sigmoid(z_pre + bz) kept in dz; rv = sigmoid(r_pre + br) * h -> xs
#pragma unroll
    for (int mt = 0; mt < 2; mt++)
#pragma unroll
        for (int nt = 0; nt < 4; nt++) {
            const int ch0 = nt * 8 + 2 * tig;
            const float bz0 = cBias[ch0], bz1 = cBias[ch0 + 1];
            const float br0 = cBias[32 + ch0], br1 = cBias[32 + ch0 + 1];
#pragma unroll
            for (int hf = 0; hf < 2; hf++) {
                int px = wpx + mt * 16 + g + hf * 8;
                int wb = px * 36 + nt * 4 + tig;
                uint32_t hh = hs[wb], hl = hs[wb + 16];
                float h0 = bf_lo(hh) + bf_lo(hl);
                float h1 = bf_hi(hh) + bf_hi(hl);
                dz[mt][nt][hf * 2 + 0] = sigmoidf_(dz[mt][nt][hf * 2 + 0] + bz0);
                dz[mt][nt][hf * 2 + 1] = sigmoidf_(dz[mt][nt][hf * 2 + 1] + bz1);
                float r0 = sigmoidf_(dr[mt][nt][hf * 2 + 0] + br0) * h0;
                float r1 = sigmoidf_(dr[mt][nt][hf * 2 + 1] + br1) * h1;
                uint32_t phi, plo;
                split2(r0, r1, phi, plo);
                xs[wb] = phi;  xs[wb + 16] = plo;
            }
        }
    __syncwarp();

    // ---- phase 2: dc += Wu * rv  (rv now lives in xs) ----
#pragma unroll
    for (int kt = 0; kt < 2; kt++) {
        uint32_t ah[2][4], al[2][4];
        LDFRAGS(xs_a, ah, al, kt)
#pragma unroll
        for (int nt = 0; nt < 4; nt++)
            mma6(dc[0][nt], dc[1][nt], ah[0], ah[1], al[0], al[1], BFRAG(5, kt, nt));
    }
    __syncwarp();   // rv reads done before overwrite

    // blend: h_t = h + z*(tanh(c_pre+bc) - h) -> xs (bf16 split)
#pragma unroll
    for (int mt = 0; mt < 2; mt++)
#pragma unroll
        for (int nt = 0; nt < 4; nt++) {
            const int ch0 = nt * 8 + 2 * tig;
            const float bc0 = cBias[64 + ch0], bc1 = cBias[64 + ch0 + 1];
#pragma unroll
            for (int hf = 0; hf < 2; hf++) {
                int px = wpx + mt * 16 + g + hf * 8;
                int wb = px * 36 + nt * 4 + tig;
                uint32_t hh = hs[wb], hl = hs[wb + 16];
                float h0 = bf_lo(hh) + bf_lo(hl);
                float h1 = bf_hi(hh) + bf_hi(hl);
                float c0 = tanhf_(dc[mt][nt][hf * 2 + 0] + bc0);
                float c1 = tanhf_(dc[mt][nt][hf * 2 + 1] + bc1);
                float t0 = fmaf(dz[mt][nt][hf * 2 + 0], c0 - h0, h0);
                float t1 = fmaf(dz[mt][nt][hf * 2 + 1], c1 - h1, h1);
                uint32_t phi, plo;
                split2(t0, t1, phi, plo);
                xs[wb] = phi;  xs[wb + 16] = plo;
            }
        }
    __syncwarp();

    // coalesced h_t store: thread reads its own pixel row from xs
    {
        float* houtb = out + NB * 32 * HW + (b * 32) * HW + p0 + tid;
#pragma unroll
        for (int w = 0; w < 16; w++) {
            int ch0 = (w >> 2) * 8 + 2 * (w & 3);
            uint32_t hh = xs[tid * 36 + w], hl = xs[tid * 36 + 16 + w];
            houtb[ch0 * HW]       = bf_lo(hh) + bf_lo(hl);
            houtb[(ch0 + 1) * HW] = bf_hi(hh) + bf_hi(hl);
        }
    }

    // ---- phase 3: y = Wo * h_t + by  (h_t in xs) ----
    float dy[2][4][4] = {};
#pragma unroll
    for (int kt = 0; kt < 2; kt++) {
        uint32_t ah[2][4], al[2][4];
        LDFRAGS(xs_a, ah, al, kt)
#pragma unroll
        for (int nt = 0; nt < 4; nt++)
            mma6(dy[0][nt], dy[1][nt], ah[0], ah[1], al[0], al[1], BFRAG(6, kt, nt));
    }
    __syncwarp();   // ht reads done before y overwrite

    // y + bias -> xs (bf16 split), then coalesced row store
#pragma unroll
    for (int mt = 0; mt < 2; mt++)
#pragma unroll
        for (int nt = 0; nt < 4; nt++) {
            const int ch0 = nt * 8 + 2 * tig;
            const float by0 = cBias[96 + ch0], by1 = cBias[96 + ch0 + 1];
#pragma unroll
            for (int hf = 0; hf < 2; hf++) {
                int px = wpx + mt * 16 + g + hf * 8;
                int wb = px * 36 + nt * 4 + tig;
                uint32_t phi, plo;
                split2(dy[mt][nt][hf * 2 + 0] + by0,
                       dy[mt][nt][hf * 2 + 1] + by1, phi, plo);
                xs[wb] = phi;  xs[wb + 16] = plo;
            }
        }
    __syncwarp();

    {
        float* youtb = out + (b * 32) * HW + p0 + tid;
#pragma unroll
        for (int w = 0; w < 16; w++) {
            int ch0 = (w >> 2) * 8 + 2 * (w & 3);
            uint32_t yh = xs[tid * 36 + w], yl = xs[tid * 36 + 16 + w];
            youtb[ch0 * HW]       = bf_lo(yh) + bf_lo(yl);
            youtb[(ch0 + 1) * HW] = bf_hi(yh) + bf_hi(yl);
        }
    }
}

extern "C" void kernel_launch(void* const* d_in, const int* in_sizes, int n_in,
                              void* d_out, int out_size) {
    const float* x    = (const float*)d_in[0];
    const float* h    = (const float*)d_in[1];
    const float* w_xz = (const float*)d_in[2];
    const float* b_xz = (const float*)d_in[3];
    const float* w_hz = (const float*)d_in[4];
    const float* b_hz = (const float*)d_in[5];
    const float* w_xr = (const float*)d_in[6];
    const float* b_xr = (const float*)d_in[7];
    const float* w_hr = (const float*)d_in[8];
    const float* b_hr = (const float*)d_in[9];
    const float* w_c  = (const float*)d_in[10];
    const float* b_c  = (const float*)d_in[11];
    const float* w_u  = (const float*)d_in[12];
    const float* b_u  = (const float*)d_in[13];
    const float* w_o  = (const float*)d_in[14];
    const float* b_o  = (const float*)d_in[15];
    float* out = (float*)d_out;

    prep_kernel<<<7, 1024>>>(w_xz, w_hz, w_xr, w_hr, w_c, w_u, w_o,
                             b_xz, b_hz, b_xr, b_hr, b_c, b_u, b_o);

    void *csym = nullptr, *gsym = nullptr;
    cudaGetSymbolAddress(&csym, cBias);
    cudaGetSymbolAddress(&gsym, g_bias_stage);
    cudaMemcpyAsync(csym, gsym, sizeof(float) * 128, cudaMemcpyDeviceToDevice);

    cudaFuncSetAttribute(gru_mma_kernel,
                         cudaFuncAttributeMaxDynamicSharedMemorySize, SMEM_TOTAL);
    gru_mma_kernel<<<4096, 128, SMEM_TOTAL>>>(x, h, out);
}

// round 12
// speedup vs baseline: 1.3631x; 1.0664x over previous
#include <cuda_runtime.h>
#include <cuda_bf16.h>
#include <cstdint>

// ConvGRU cell via warp-level mma.sync (HMMA bf16, f32 accum), compute_103-safe.
// fp32 accuracy via bf16 hi/lo split (3 terms: Ah*Wh + Al*Wh + Ah*Wl).
// R12: B fragments are read straight from global memory (__ldg, L1-resident
// 28.7KB working set) instead of a per-CTA smem copy -> smem 64KB -> 36.9KB,
// and __launch_bounds__(128,4) caps regs at 128 => 4 CTAs / 16 warps per SM
// (R11 was latency-bound at 12 warps, all pipes < 50%). No cross-warp smem
// sharing remains, so there is no __syncthreads at all.

#define HW 65536        // 256*256
#define NB 8

// smem: xs 18432 | hs 18432 = 36864 B
#define TILE_BYTES 18432
#define SMEM_TOTAL (2 * TILE_BYTES)

__device__ __align__(16) uint32_t g_wfrag[7168];
__device__ float g_bias_stage[128];
__constant__ float cBias[128];   // [bz | br | bc | by]

__device__ __forceinline__ float sigmoidf_(float a) {
    a = fminf(fmaxf(a, -30.f), 30.f);
    float e = __expf(-a);
    return __fdividef(1.f, 1.f + e);
}
__device__ __forceinline__ float tanhf_(float a) {
    a = fminf(fmaxf(a, -15.f), 15.f);
    float e = __expf(-2.f * a);
    return (1.f - e) * __fdividef(1.f, 1.f + e);
}
__device__ __forceinline__ void split2(float a, float b, uint32_t& hi, uint32_t& lo) {
    __nv_bfloat16 ha = __float2bfloat16(a);
    __nv_bfloat16 hb = __float2bfloat16(b);
    __nv_bfloat16 la = __float2bfloat16(a - __bfloat162float(ha));
    __nv_bfloat16 lb = __float2bfloat16(b - __bfloat162float(hb));
    hi = (uint32_t)__bfloat16_as_ushort(ha) | ((uint32_t)__bfloat16_as_ushort(hb) << 16);
    lo = (uint32_t)__bfloat16_as_ushort(la) | ((uint32_t)__bfloat16_as_ushort(lb) << 16);
}
__device__ __forceinline__ float bf_lo(uint32_t v) {
    return __bfloat162float(__ushort_as_bfloat16((unsigned short)(v & 0xFFFF)));
}
__device__ __forceinline__ float bf_hi(uint32_t v) {
    return __bfloat162float(__ushort_as_bfloat16((unsigned short)(v >> 16)));
}
__device__ __forceinline__ uint32_t smem_u32(const void* p) {
    uint32_t a;
    asm("{ .reg .u64 t; cvta.to.shared.u64 t, %1; cvt.u32.u64 %0, t; }"
        : "=r"(a) : "l"(p));
    return a;
}
__device__ __forceinline__ void ldmA(uint32_t a[4], uint32_t addr) {
    asm volatile("ldmatrix.sync.aligned.m8n8.x4.shared.b16 {%0,%1,%2,%3}, [%4];"
                 : "=r"(a[0]), "=r"(a[1]), "=r"(a[2]), "=r"(a[3]) : "r"(addr));
}
__device__ __forceinline__ void mma16816(float d[4], const uint32_t a[4],
                                         uint32_t b0, uint32_t b1) {
    asm volatile(
        "mma.sync.aligned.m16n8k16.row.col.f32.bf16.bf16.f32 "
        "{%0,%1,%2,%3}, {%4,%5,%6,%7}, {%8,%9}, {%0,%1,%2,%3};"
        : "+f"(d[0]), "+f"(d[1]), "+f"(d[2]), "+f"(d[3])
        : "r"(a[0]), "r"(a[1]), "r"(a[2]), "r"(a[3]), "r"(b0), "r"(b1));
}
// 3-term split MMA group: d[mt][nt] += Ah*Bh + Al*Bh + Ah*Bl
__device__ __forceinline__ void mma6(float d0[4], float d1[4],
                                     const uint32_t ah0[4], const uint32_t ah1[4],
                                     const uint32_t al0[4], const uint32_t al1[4],
                                     uint4 b) {
    mma16816(d0, ah0, b.x, b.y);
    mma16816(d1, ah1, b.x, b.y);
    mma16816(d0, al0, b.x, b.y);
    mma16816(d1, al1, b.x, b.y);
    mma16816(d0, ah0, b.z, b.w);
    mma16816(d1, ah1, b.z, b.w);
}

// prep: B fragments packed uint4 {bh0,bh1,bl0,bl1} per (m,kt,nt,lane).
__global__ void prep_kernel(
    const float* __restrict__ w_xz, const float* __restrict__ w_hz,
    const float* __restrict__ w_xr, const float* __restrict__ w_hr,
    const float* __restrict__ w_c,  const float* __restrict__ w_u,
    const float* __restrict__ w_o,
    const float* __restrict__ b_xz, const float* __restrict__ b_hz,
    const float* __restrict__ b_xr, const float* __restrict__ b_hr,
    const float* __restrict__ b_c,  const float* __restrict__ b_u,
    const float* __restrict__ b_o)
{
    int m = blockIdx.x;                  // 0..6
    int t = threadIdx.x;                 // 0..1023
    int lane = t & 31;
    int reg  = (t >> 5) & 1;
    int nt   = (t >> 6) & 3;
    int kt   = (t >> 8) & 1;
    int term = (t >> 9) & 1;
    int g = lane >> 2, tig = lane & 3;
    const float* Wm = (m == 0) ? w_xz : (m == 1) ? w_hz : (m == 2) ? w_xr :
                      (m == 3) ? w_hr : (m == 4) ? w_c  : (m == 5) ? w_u : w_o;
    int n  = nt * 8 + g;
    int kk = kt * 16 + 2 * tig + reg * 8;
    float w0 = Wm[n * 32 + kk];
    float w1 = Wm[n * 32 + kk + 1];
    __nv_bfloat16 h0 = __float2bfloat16(w0);
    __nv_bfloat16 h1 = __float2bfloat16(w1);
    uint32_t val;
    if (term == 0) {
        val = (uint32_t)__bfloat16_as_ushort(h0) |
              ((uint32_t)__bfloat16_as_ushort(h1) << 16);
    } else {
        __nv_bfloat16 l0 = __float2bfloat16(w0 - __bfloat162float(h0));
        __nv_bfloat16 l1 = __float2bfloat16(w1 - __bfloat162float(h1));
        val = (uint32_t)__bfloat16_as_ushort(l0) |
              ((uint32_t)__bfloat16_as_ushort(l1) << 16);
    }
    // uint4: [(m*2+kt)*4+nt][lane] -> {bh0,bh1,bl0,bl1}
    g_wfrag[((((m * 2 + kt) * 4 + nt) * 32) + lane) * 4 + term * 2 + reg] = val;
    if (m == 0 && t < 32) {
        g_bias_stage[ 0 + t] = b_xz[t] + b_hz[t];
        g_bias_stage[32 + t] = b_xr[t] + b_hr[t];
        g_bias_stage[64 + t] = b_c[t]  + b_u[t];
        g_bias_stage[96 + t] = b_o[t];
    }
}

__global__ void __launch_bounds__(128, 4) gru_mma_kernel(
    const float* __restrict__ x, const float* __restrict__ h,
    float* __restrict__ out)
{
    extern __shared__ __align__(16) unsigned char dsm[];
    uint32_t* xs = (uint32_t*)dsm;                            // 36 u32 / row
    uint32_t* hs = (uint32_t*)(dsm + TILE_BYTES);
    const uint4* __restrict__ wfv = (const uint4*)g_wfrag;    // L1-resident

    const int tid = threadIdx.x;
    const int wid = tid >> 5, lane = tid & 31;
    const int g = lane >> 2, tig = lane & 3;
    const int wpx = wid * 32;
    const int l15 = lane & 15, lhi = lane >> 4;

    const uint32_t xs_a = smem_u32(xs);
    const uint32_t hs_a = smem_u32(hs);

    const int gp0 = blockIdx.x * 128;   // 4096 blocks cover 524288 px
    const int b   = gp0 >> 16;
    const int p0  = gp0 & 65535;
    const float* xb = x + (b * 32) * HW + p0 + tid;
    const float* hb = h + (b * 32) * HW + p0 + tid;

    // ---- load x,h (coalesced), split, fill tiles (row = own pixel) ----
#pragma unroll
    for (int j = 0; j < 16; j++) {
        float a0 = xb[(2 * j) * HW], a1 = xb[(2 * j + 1) * HW];
        float c0 = hb[(2 * j) * HW], c1 = hb[(2 * j + 1) * HW];
        uint32_t phi, plo;
        split2(a0, a1, phi, plo);
        xs[tid * 36 + j] = phi;  xs[tid * 36 + 16 + j] = plo;
        split2(c0, c1, phi, plo);
        hs[tid * 36 + j] = phi;  hs[tid * 36 + 16 + j] = plo;
    }
    __syncwarp();   // tiles are warp-local; no cross-warp sharing anywhere

#define LDFRAGS(base_a, ah, al, kt)                                            \
    {                                                                          \
        uint32_t ca = (uint32_t)(((kt) * 16 + lhi * 8) * 2);                   \
        _Pragma("unroll")                                                      \
        for (int mt = 0; mt < 2; mt++) {                                       \
            uint32_t rowb = (base_a) + (uint32_t)((wpx + mt * 16 + l15) * 144);\
            ldmA((ah)[mt], rowb + ca);                                         \
            ldmA((al)[mt], rowb + ca + 64);                                    \
        }                                                                      \
    }

#define BFRAG(m, kt, nt) __ldg(&wfv[(((m) * 2 + (kt)) * 4 + (nt)) * 32 + lane])

    // ---- phase 1: z_pre, r_pre, and the Wc*x part of the candidate ----
    float dz[2][4][4] = {}, dr[2][4][4] = {}, dc[2][4][4] = {};
#pragma unroll
    for (int kt = 0; kt < 2; kt++) {
        uint32_t ah[2][4], al[2][4];
        LDFRAGS(xs_a, ah, al, kt)
#pragma unroll
        for (int nt = 0; nt < 4; nt++) {
            mma6(dz[0][nt], dz[1][nt], ah[0], ah[1], al[0], al[1], BFRAG(0, kt, nt));
            mma6(dr[0][nt], dr[1][nt], ah[0], ah[1], al[0], al[1], BFRAG(2, kt, nt));
            mma6(dc[0][nt], dc[1][nt], ah[0], ah[1], al[0], al[1], BFRAG(4, kt, nt));
        }
        LDFRAGS(hs_a, ah, al, kt)
#pragma unroll
        for (int nt = 0; nt < 4; nt++) {
            mma6(dz[0][nt], dz[1][nt], ah[0], ah[1], al[0], al[1], BFRAG(1, kt, nt));
            mma6(dr[0][nt], dr[1][nt], ah[0], ah[1], al[0], al[1], BFRAG(3, kt, nt));
        }
    }
    __syncwarp();   // all xs ldmatrix reads done -> xs reusable

    // z = sigmoid(z_pre + bz) kept in dz; rv = sigmoid(r_pre + br) * h -> xs
#pragma unroll
    for (int mt = 0; mt < 2; mt++)
#pragma unroll
        for (int nt = 0; nt < 4; nt++) {
            const int ch0 = nt * 8 + 2 * tig;
            const float bz0 = cBias[ch0], bz1 = cBias[ch0 + 1];
            const float br0 = cBias[32 + ch0], br1 = cBias[32 + ch0 + 1];
#pragma unroll
            for (int hf = 0; hf < 2; hf++) {
                int px = wpx + mt * 16 + g + hf * 8;
                int wb = px * 36 + nt * 4 + tig;
                uint32_t hh = hs[wb], hl = hs[wb + 16];
                float h0 = bf_lo(hh) + bf_lo(hl);
                float h1 = bf_hi(hh) + bf_hi(hl);
                dz[mt][nt][hf * 2 + 0] = sigmoidf_(dz[mt][nt][hf * 2 + 0] + bz0);
                dz[mt][nt][hf * 2 + 1] = sigmoidf_(dz[mt][nt][hf * 2 + 1] + bz1);
                float r0 = sigmoidf_(dr[mt][nt][hf * 2 + 0] + br0) * h0;
                float r1 = sigmoidf_(dr[mt][nt][hf * 2 + 1] + br1) * h1;
                uint32_t phi, plo;
                split2(r0, r1, phi, plo);
                xs[wb] = phi;  xs[wb + 16] = plo;
            }
        }
    __syncwarp();

    // ---- phase 2: dc += Wu * rv  (rv now lives in xs) ----
#pragma unroll
    for (int kt = 0; kt < 2; kt++) {
        uint32_t ah[2][4], al[2][4];
        LDFRAGS(xs_a, ah, al, kt)
#pragma unroll
        for (int nt = 0; nt < 4; nt++)
            mma6(dc[0][nt], dc[1][nt], ah[0], ah[1], al[0], al[1], BFRAG(5, kt, nt));
    }
    __syncwarp();   // rv reads done before overwrite

    // blend: h_t = h + z*(tanh(c_pre+bc) - h) -> xs (bf16 split)
#pragma unroll
    for (int mt = 0; mt < 2; mt++)
#pragma unroll
        for (int nt = 0; nt < 4; nt++) {
            const int ch0 = nt * 8 + 2 * tig;
            const float bc0 = cBias[64 + ch0], bc1 = cBias[64 + ch0 + 1];
#pragma unroll
            for (int hf = 0; hf < 2; hf++) {
                int px = wpx + mt * 16 + g + hf * 8;
                int wb = px * 36 + nt * 4 + tig;
                uint32_t hh = hs[wb], hl = hs[wb + 16];
                float h0 = bf_lo(hh) + bf_lo(hl);
                float h1 = bf_hi(hh) + bf_hi(hl);
                float c0 = tanhf_(dc[mt][nt][hf * 2 + 0] + bc0);
                float c1 = tanhf_(dc[mt][nt][hf * 2 + 1] + bc1);
                float t0 = fmaf(dz[mt][nt][hf * 2 + 0], c0 - h0, h0);
                float t1 = fmaf(dz[mt][nt][hf * 2 + 1], c1 - h1, h1);
                uint32_t phi, plo;
                split2(t0, t1, phi, plo);
                xs[wb] = phi;  xs[wb + 16] = plo;
            }
        }
    __syncwarp();

    // coalesced h_t store: thread reads its own pixel row from xs
    {
        float* houtb = out + NB * 32 * HW + (b * 32) * HW + p0 + tid;
#pragma unroll
        for (int w = 0; w < 16; w++) {
            int ch0 = (w >> 2) * 8 + 2 * (w & 3);
            uint32_t hh = xs[tid * 36 + w], hl = xs[tid * 36 + 16 + w];
            houtb[ch0 * HW]       = bf_lo(hh) + bf_lo(hl);
            houtb[(ch0 + 1) * HW] = bf_hi(hh) + bf_hi(hl);
        }
    }

    // ---- phase 3: y = Wo * h_t + by  (h_t in xs) ----
    float dy[2][4][4] = {};
#pragma unroll
    for (int kt = 0; kt < 2; kt++) {
        uint32_t ah[2][4], al[2][4];
        LDFRAGS(xs_a, ah, al, kt)
#pragma unroll
        for (int nt = 0; nt < 4; nt++)
            mma6(dy[0][nt], dy[1][nt], ah[0], ah[1], al[0], al[1], BFRAG(6, kt, nt));
    }
    __syncwarp();   // ht reads done before y overwrite

    // y + bias -> xs (bf16 split), then coalesced row store
#pragma unroll
    for (int mt = 0; mt < 2; mt++)
#pragma unroll
        for (int nt = 0; nt < 4; nt++) {
            const int ch0 = nt * 8 + 2 * tig;
            const float by0 = cBias[96 + ch0], by1 = cBias[96 + ch0 + 1];
#pragma unroll
            for (int hf = 0; hf < 2; hf++) {
                int px = wpx + mt * 16 + g + hf * 8;
                int wb = px * 36 + nt * 4 + tig;
                uint32_t phi, plo;
                split2(dy[mt][nt][hf * 2 + 0] + by0,
                       dy[mt][nt][hf * 2 + 1] + by1, phi, plo);
                xs[wb] = phi;  xs[wb + 16] = plo;
            }
        }
    __syncwarp();

    {
        float* youtb = out + (b * 32) * HW + p0 + tid;
#pragma unroll
        for (int w = 0; w < 16; w++) {
            int ch0 = (w >> 2) * 8 + 2 * (w & 3);
            uint32_t yh = xs[tid * 36 + w], yl = xs[tid * 36 + 16 + w];
            youtb[ch0 * HW]       = bf_lo(yh) + bf_lo(yl);
            youtb[(ch0 + 1) * HW] = bf_hi(yh) + bf_hi(yl);
        }
    }
}

extern "C" void kernel_launch(void* const* d_in, const int* in_sizes, int n_in,
                              void* d_out, int out_size) {
    const float* x    = (const float*)d_in[0];
    const float* h    = (const float*)d_in[1];
    const float* w_xz = (const float*)d_in[2];
    const float* b_xz = (const float*)d_in[3];
    const float* w_hz = (const float*)d_in[4];
    const float* b_hz = (const float*)d_in[5];
    const float* w_xr = (const float*)d_in[6];
    const float* b_xr = (const float*)d_in[7];
    const float* w_hr = (const float*)d_in[8];
    const float* b_hr = (const float*)d_in[9];
    const float* w_c  = (const float*)d_in[10];
    const float* b_c  = (const float*)d_in[11];
    const float* w_u  = (const float*)d_in[12];
    const float* b_u  = (const float*)d_in[13];
    const float* w_o  = (const float*)d_in[14];
    const float* b_o  = (const float*)d_in[15];
    float* out = (float*)d_out;

    prep_kernel<<<7, 1024>>>(w_xz, w_hz, w_xr, w_hr, w_c, w_u, w_o,
                             b_xz, b_hz, b_xr, b_hr, b_c, b_u, b_o);

    void *csym = nullptr, *gsym = nullptr;
    cudaGetSymbolAddress(&csym, cBias);
    cudaGetSymbolAddress(&gsym, g_bias_stage);
    cudaMemcpyAsync(csym, gsym, sizeof(float) * 128, cudaMemcpyDeviceToDevice);

    cudaFuncSetAttribute(gru_mma_kernel,
                         cudaFuncAttributeMaxDynamicSharedMemorySize, SMEM_TOTAL);
    gru_mma_kernel<<<4096, 128, SMEM_TOTAL>>>(x, h, out);
}

// round 13
// speedup vs baseline: 1.4582x; 1.0698x over previous
#include <cuda_runtime.h>
#include <cuda_bf16.h>
#include <cstdint>

// ConvGRUCell via warp-level mma.sync (HMMA bf16, f32 accum), compute_103-safe.
// fp32 accuracy via bf16 hi/lo split (3 terms: Ah*Wh + Al*Wh + Ah*Wl).
// R13: MMA issue order is term-major so consecutive asm-volatile HMMAs hit 8
// independent accumulators (dependency distance 2 -> 8 instructions). R12's
// profile showed warp-level dependency stalls (issue stuck at 47% despite 16
// warps/SM): the old order reused each accumulator after 2 instructions.
// B fragments via __ldg from a L1-resident 28.7KB global array; smem 36.9KB,
// __launch_bounds__(128,4) => 4 CTAs / 16 warps per SM; no __syncthreads.

#define HW 65536        // 256*256
#define NB 8

#define TILE_BYTES 18432
#define SMEM_TOTAL (2 * TILE_BYTES)

__device__ __align__(16) uint32_t g_wfrag[7168];
__device__ float g_bias_stage[128];
__constant__ float cBias[128];   // [bz | br | bc | by]

__device__ __forceinline__ float sigmoidf_(float a) {
    a = fminf(fmaxf(a, -30.f), 30.f);
    float e = __expf(-a);
    return __fdividef(1.f, 1.f + e);
}
__device__ __forceinline__ float tanhf_(float a) {
    a = fminf(fmaxf(a, -15.f), 15.f);
    float e = __expf(-2.f * a);
    return (1.f - e) * __fdividef(1.f, 1.f + e);
}
__device__ __forceinline__ void split2(float a, float b, uint32_t& hi, uint32_t& lo) {
    __nv_bfloat16 ha = __float2bfloat16(a);
    __nv_bfloat16 hb = __float2bfloat16(b);
    __nv_bfloat16 la = __float2bfloat16(a - __bfloat162float(ha));
    __nv_bfloat16 lb = __float2bfloat16(b - __bfloat162float(hb));
    hi = (uint32_t)__bfloat16_as_ushort(ha) | ((uint32_t)__bfloat16_as_ushort(hb) << 16);
    lo = (uint32_t)__bfloat16_as_ushort(la) | ((uint32_t)__bfloat16_as_ushort(lb) << 16);
}
__device__ __forceinline__ float bf_lo(uint32_t v) {
    return __bfloat162float(__ushort_as_bfloat16((unsigned short)(v & 0xFFFF)));
}
__device__ __forceinline__ float bf_hi(uint32_t v) {
    return __bfloat162float(__ushort_as_bfloat16((unsigned short)(v >> 16)));
}
__device__ __forceinline__ uint32_t smem_u32(const void* p) {
    uint32_t a;
    asm("{ .reg .u64 t; cvta.to.shared.u64 t, %1; cvt.u32.u64 %0, t; }"
        : "=r"(a) : "l"(p));
    return a;
}
__device__ __forceinline__ void ldmA(uint32_t a[4], uint32_t addr) {
    asm volatile("ldmatrix.sync.aligned.m8n8.x4.shared.b16 {%0,%1,%2,%3}, [%4];"
                 : "=r"(a[0]), "=r"(a[1]), "=r"(a[2]), "=r"(a[3]) : "r"(addr));
}
__device__ __forceinline__ void mma16816(float d[4], const uint32_t a[4],
                                         uint32_t b0, uint32_t b1) {
    asm volatile(
        "mma.sync.aligned.m16n8k16.row.col.f32.bf16.bf16.f32 "
        "{%0,%1,%2,%3}, {%4,%5,%6,%7}, {%8,%9}, {%0,%1,%2,%3};"
        : "+f"(d[0]), "+f"(d[1]), "+f"(d[2]), "+f"(d[3])
        : "r"(a[0]), "r"(a[1]), "r"(a[2]), "r"(a[3]), "r"(b0), "r"(b1));
}

// prep: B fragments packed uint4 {bh0,bh1,bl0,bl1} per (m,kt,nt,lane).
__global__ void prep_kernel(
    const float* __restrict__ w_xz, const float* __restrict__ w_hz,
    const float* __restrict__ w_xr, const float* __restrict__ w_hr,
    const float* __restrict__ w_c,  const float* __restrict__ w_u,
    const float* __restrict__ w_o,
    const float* __restrict__ b_xz, const float* __restrict__ b_hz,
    const float* __restrict__ b_xr, const float* __restrict__ b_hr,
    const float* __restrict__ b_c,  const float* __restrict__ b_u,
    const float* __restrict__ b_o)
{
    int m = blockIdx.x;                  // 0..6
    int t = threadIdx.x;                 // 0..1023
    int lane = t & 31;
    int reg  = (t >> 5) & 1;
    int nt   = (t >> 6) & 3;
    int kt   = (t >> 8) & 1;
    int term = (t >> 9) & 1;
    int g = lane >> 2, tig = lane & 3;
    const float* Wm = (m == 0) ? w_xz : (m == 1) ? w_hz : (m == 2) ? w_xr :
                      (m == 3) ? w_hr : (m == 4) ? w_c  : (m == 5) ? w_u : w_o;
    int n  = nt * 8 + g;
    int kk = kt * 16 + 2 * tig + reg * 8;
    float w0 = Wm[n * 32 + kk];
    float w1 = Wm[n * 32 + kk + 1];
    __nv_bfloat16 h0 = __float2bfloat16(w0);
    __nv_bfloat16 h1 = __float2bfloat16(w1);
    uint32_t val;
    if (term == 0) {
        val = (uint32_t)__bfloat16_as_ushort(h0) |
              ((uint32_t)__bfloat16_as_ushort(h1) << 16);
    } else {
        __nv_bfloat16 l0 = __float2bfloat16(w0 - __bfloat162float(h0));
        __nv_bfloat16 l1 = __float2bfloat16(w1 - __bfloat162float(h1));
        val = (uint32_t)__bfloat16_as_ushort(l0) |
              ((uint32_t)__bfloat16_as_ushort(l1) << 16);
    }
    // uint4: [(m*2+kt)*4+nt][lane] -> {bh0,bh1,bl0,bl1}
    g_wfrag[((((m * 2 + kt) * 4 + nt) * 32) + lane) * 4 + term * 2 + reg] = val;
    if (m == 0 && t < 32) {
        g_bias_stage[ 0 + t] = b_xz[t] + b_hz[t];
        g_bias_stage[32 + t] = b_xr[t] + b_hr[t];
        g_bias_stage[64 + t] = b_c[t]  + b_u[t];
        g_bias_stage[96 + t] = b_o[t];
    }
}

__global__ void __launch_bounds__(128, 4) gru_mma_kernel(
    const float* __restrict__ x, const float* __restrict__ h,
    float* __restrict__ out)
{
    extern __shared__ __align__(16) unsigned char dsm[];
    uint32_t* xs = (uint32_t*)dsm;                            // 36 u32 / row
    uint32_t* hs = (uint32_t*)(dsm + TILE_BYTES);
    const uint4* __restrict__ wfv = (const uint4*)g_wfrag;    // L1-resident

    const int tid = threadIdx.x;
    const int wid = tid >> 5, lane = tid & 31;
    const int g = lane >> 2, tig = lane & 3;
    const int wpx = wid * 32;
    const int l15 = lane & 15, lhi = lane >> 4;

    const uint32_t xs_a = smem_u32(xs);
    const uint32_t hs_a = smem_u32(hs);

    const int gp0 = blockIdx.x * 128;   // 4096 blocks cover 524288 px
    const int b   = gp0 >> 16;
    const int p0  = gp0 & 65535;
    const float* xb = x + (b * 32) * HW + p0 + tid;
    const float* hb = h + (b * 32) * HW + p0 + tid;

    // ---- load x,h (coalesced), split, fill tiles (row = own pixel) ----
#pragma unroll
    for (int j = 0; j < 16; j++) {
        float a0 = xb[(2 * j) * HW], a1 = xb[(2 * j + 1) * HW];
        float c0 = hb[(2 * j) * HW], c1 = hb[(2 * j + 1) * HW];
        uint32_t phi, plo;
        split2(a0, a1, phi, plo);
        xs[tid * 36 + j] = phi;  xs[tid * 36 + 16 + j] = plo;
        split2(c0, c1, phi, plo);
        hs[tid * 36 + j] = phi;  hs[tid * 36 + 16 + j] = plo;
    }
    __syncwarp();   // tiles are warp-local

#define LDFRAGS(base_a, ah, al, kt)                                            \
    {                                                                          \
        uint32_t ca = (uint32_t)(((kt) * 16 + lhi * 8) * 2);                   \
        _Pragma("unroll")                                                      \
        for (int mt = 0; mt < 2; mt++) {                                       \
            uint32_t rowb = (base_a) + (uint32_t)((wpx + mt * 16 + l15) * 144);\
            ldmA((ah)[mt], rowb + ca);                                         \
            ldmA((al)[mt], rowb + ca + 64);                                    \
        }                                                                      \
    }

#define BFRAG(m, kt, nt) __ldg(&wfv[(((m) * 2 + (kt)) * 4 + (nt)) * 32 + lane])

// One matrix, one kt: 24 MMAs issued term-major so consecutive HMMAs touch 8
// independent accumulators (dep distance 8 instead of 2).
#define MMA_MAT(d, m, kt, ah, al)                                              \
    {                                                                          \
        _Pragma("unroll")                                                      \
        for (int nt = 0; nt < 4; nt++) {                                       \
            uint4 bq = BFRAG(m, kt, nt);                                       \
            mma16816((d)[0][nt], (ah)[0], bq.x, bq.y);                         \
            mma16816((d)[1][nt], (ah)[1], bq.x, bq.y);                         \
        }                                                                      \
        _Pragma("unroll")                                                      \
        for (int nt = 0; nt < 4; nt++) {                                       \
            uint4 bq = BFRAG(m, kt, nt);                                       \
            mma16816((d)[0][nt], (al)[0], bq.x, bq.y);                         \
            mma16816((d)[1][nt], (al)[1], bq.x, bq.y);                         \
        }                                                                      \
        _Pragma("unroll")                                                      \
        for (int nt = 0; nt < 4; nt++) {                                       \
            uint4 bq = BFRAG(m, kt, nt);                                       \
            mma16816((d)[0][nt], (ah)[0], bq.z, bq.w);                         \
            mma16816((d)[1][nt], (ah)[1], bq.z, bq.w);                         \
        }                                                                      \
    }

    // ---- phase 1: z_pre, r_pre, and the Wc*x part of the candidate ----
    float dz[2][4][4] = {}, dr[2][4][4] = {}, dc[2][4][4] = {};
#pragma unroll
    for (int kt = 0; kt < 2; kt++) {
        uint32_t ah[2][4], al[2][4];
        LDFRAGS(xs_a, ah, al, kt)
        MMA_MAT(dz, 0, kt, ah, al)
        MMA_MAT(dr, 2, kt, ah, al)
        MMA_MAT(dc, 4, kt, ah, al)
        LDFRAGS(hs_a, ah, al, kt)
        MMA_MAT(dz, 1, kt, ah, al)
        MMA_MAT(dr, 3, kt, ah, al)
    }
    __syncwarp();   // all xs ldmatrix reads done -> xs reusable

    // z = sigmoid(z_pre + bz) kept in dz; rv = sigmoid(r_pre + br) * h -> xs
#pragma unroll
    for (int mt = 0; mt < 2; mt++)
#pragma unroll
        for (int nt = 0; nt < 4; nt++) {
            const int ch0 = nt * 8 + 2 * tig;
            const float bz0 = cBias[ch0], bz1 = cBias[ch0 + 1];
            const float br0 = cBias[32 + ch0], br1 = cBias[32 + ch0 + 1];
#pragma unroll
            for (int hf = 0; hf < 2; hf++) {
                int px = wpx + mt * 16 + g + hf * 8;
                int wb = px * 36 + nt * 4 + tig;
                uint32_t hh = hs[wb], hl = hs[wb + 16];
                float h0 = bf_lo(hh) + bf_lo(hl);
                float h1 = bf_hi(hh) + bf_hi(hl);
                dz[mt][nt][hf * 2 + 0] = sigmoidf_(dz[mt][nt][hf * 2 + 0] + bz0);
                dz[mt][nt][hf * 2 + 1] = sigmoidf_(dz[mt][nt][hf * 2 + 1] + bz1);
                float r0 = sigmoidf_(dr[mt][nt][hf * 2 + 0] + br0) * h0;
                float r1 = sigmoidf_(dr[mt][nt][hf * 2 + 1] + br1) * h1;
                uint32_t phi, plo;
                split2(r0, r1, phi, plo);
                xs[wb] = phi;  xs[wb + 16] = plo;
            }
        }
    __syncwarp();

    // ---- phase 2: dc += Wu * rv  (rv in xs) ----
#pragma unroll
    for (int kt = 0; kt < 2; kt++) {
        uint32_t ah[2][4], al[2][4];
        LDFRAGS(xs_a, ah, al, kt)
        MMA_MAT(dc, 5, kt, ah, al)
    }
    __syncwarp();   // rv reads done before overwrite

    // blend: h_t = h + z*(tanh(c_pre+bc) - h) -> xs (bf16 split)
#pragma unroll
    for (int mt = 0; mt < 2; mt++)
#pragma unroll
        for (int nt = 0; nt < 4; nt++) {
            const int ch0 = nt * 8 + 2 * tig;
            const float bc0 = cBias[64 + ch0], bc1 = cBias[64 + ch0 + 1];
#pragma unroll
            for (int hf = 0; hf < 2; hf++) {
                int px = wpx + mt * 16 + g + hf * 8;
                int wb = px * 36 + nt * 4 + tig;
                uint32_t hh = hs[wb], hl = hs[wb + 16];
                float h0 = bf_lo(hh) + bf_lo(hl);
                float h1 = bf_hi(hh) + bf_hi(hl);
                float c0 = tanhf_(dc[mt][nt][hf * 2 + 0] + bc0);
                float c1 = tanhf_(dc[mt][nt][hf * 2 + 1] + bc1);
                float t0 = fmaf(dz[mt][nt][hf * 2 + 0], c0 - h0, h0);
                float t1 = fmaf(dz[mt][nt][hf * 2 + 1], c1 - h1, h1);
                uint32_t phi, plo;
                split2(t0, t1, phi, plo);
                xs[wb] = phi;  xs[wb + 16] = plo;
            }
        }
    __syncwarp();

    // coalesced h_t store
    {
        float* houtb = out + NB * 32 * HW + (b * 32) * HW + p0 + tid;
#pragma unroll
        for (int w = 0; w < 16; w++) {
            int ch0 = (w >> 2) * 8 + 2 * (w & 3);
            uint32_t hh = xs[tid * 36 + w], hl = xs[tid * 36 + 16 + w];
            houtb[ch0 * HW]       = bf_lo(hh) + bf_lo(hl);
            houtb[(ch0 + 1) * HW] = bf_hi(hh) + bf_hi(hl);
        }
    }

    // ---- phase 3: y = Wo * h_t + by  (h_t in xs) ----
    float dy[2][4][4] = {};
#pragma unroll
    for (int kt = 0; kt < 2; kt++) {
        uint32_t ah[2][4], al[2][4];
        LDFRAGS(xs_a, ah, al, kt)
        MMA_MAT(dy, 6, kt, ah, al)
    }
    __syncwarp();   // ht reads done before y overwrite

    // y + bias -> xs (bf16 split), then coalesced row store
#pragma unroll
    for (int mt = 0; mt < 2; mt++)
#pragma unroll
        for (int nt = 0; nt < 4; nt++) {
            const int ch0 = nt * 8 + 2 * tig;
            const float by0 = cBias[96 + ch0], by1 = cBias[96 + ch0 + 1];
#pragma unroll
            for (int hf = 0; hf < 2; hf++) {
                int px = wpx + mt * 16 + g + hf * 8;
                int wb = px * 36 + nt * 4 + tig;
                uint32_t phi, plo;
                split2(dy[mt][nt][hf * 2 + 0] + by0,
                       dy[mt][nt][hf * 2 + 1] + by1, phi, plo);
                xs[wb] = phi;  xs[wb + 16] = plo;
            }
        }
    __syncwarp();

    {
        float* youtb = out + (b * 32) * HW + p0 + tid;
#pragma unroll
        for (int w = 0; w < 16; w++) {
            int ch0 = (w >> 2) * 8 + 2 * (w & 3);
            uint32_t yh = xs[tid * 36 + w], yl = xs[tid * 36 + 16 + w];
            youtb[ch0 * HW]       = bf_lo(yh) + bf_lo(yl);
            youtb[(ch0 + 1) * HW] = bf_hi(yh) + bf_hi(yl);
        }
    }
}

extern "C" void kernel_launch(void* const* d_in, const int* in_sizes, int n_in,
                              void* d_out, int out_size) {
    const float* x    = (const float*)d_in[0];
    const float* h    = (const float*)d_in[1];
    const float* w_xz = (const float*)d_in[2];
    const float* b_xz = (const float*)d_in[3];
    const float* w_hz = (const float*)d_in[4];
    const float* b_hz = (const float*)d_in[5];
    const float* w_xr = (const float*)d_in[6];
    const float* b_xr = (const float*)d_in[7];
    const float* w_hr = (const float*)d_in[8];
    const float* b_hr = (const float*)d_in[9];
    const float* w_c  = (const float*)d_in[10];
    const float* b_c  = (const float*)d_in[11];
    const float* w_u  = (const float*)d_in[12];
    const float* b_u  = (const float*)d_in[13];
    const float* w_o  = (const float*)d_in[14];
    const float* b_o  = (const float*)d_in[15];
    float* out = (float*)d_out;

    prep_kernel<<<7, 1024>>>(w_xz, w_hz, w_xr, w_hr, w_c, w_u, w_o,
                             b_xz, b_hz, b_xr, b_hr, b_c, b_u, b_o);

    void *csym = nullptr, *gsym = nullptr;
    cudaGetSymbolAddress(&csym, cBias);
    cudaGetSymbolAddress(&gsym, g_bias_stage);
    cudaMemcpyAsync(csym, gsym, sizeof(float) * 128, cudaMemcpyDeviceToDevice);

    cudaFuncSetAttribute(gru_mma_kernel,
                         cudaFuncAttributeMaxDynamicSharedMemorySize, SMEM_TOTAL);
    gru_mma_kernel<<<4096, 128, SMEM_TOTAL>>>(x, h, out);
}

// round 14
// speedup vs baseline: 1.5473x; 1.0611x over previous
#include <cuda_runtime.h>
#include <cuda_bf16.h>
#include <cstdint>

// ConvGRUCell via warp-level mma.sync (HMMA bf16, f32 accum), compute_103-safe.
// fp32 accuracy via bf16 hi/lo split (3 terms: Ah*Wh + Al*Wh + Ah*Wl).
// R14: (a) third smem tile restored (55.3KB x 4 CTAs fits 228KB) so phase 1
// holds only dz+dr (64 acc) and all 4 B-fragment uint4s are register-cached
// across the 3 split terms -> B LDG.128 count 168 -> 56 per warp (top L1
// contributor in R13); (b) bf16 split/unpack via prmt/shift bit tricks
// (truncation; residual still exact) instead of cvt chains.

#define HW 65536        // 256*256
#define NB 8

#define TILE_BYTES 18432
#define SMEM_TOTAL (3 * TILE_BYTES)     // 55296 B -> 4 CTAs/SM

__device__ __align__(16) uint32_t g_wfrag[7168];
__device__ float g_bias_stage[128];
__constant__ float cBias[128];   // [bz | br | bc | by]

__device__ __forceinline__ float sigmoidf_(float a) {
    a = fminf(fmaxf(a, -30.f), 30.f);
    float e = __expf(-a);
    return __fdividef(1.f, 1.f + e);
}
__device__ __forceinline__ float tanhf_(float a) {
    a = fminf(fmaxf(a, -15.f), 15.f);
    float e = __expf(-2.f * a);
    return (1.f - e) * __fdividef(1.f, 1.f + e);
}
// bit-trick bf16x2 split: hi = {trunc_bf16(b), trunc_bf16(a)},
// lo = {trunc_bf16(b-hi_b), trunc_bf16(a-hi_a)}. Truncation (not RN) --
// the lo term captures the residual exactly, so pair error ~2^-16.
__device__ __forceinline__ void split2(float a, float b, uint32_t& hi, uint32_t& lo) {
    uint32_t ab = __float_as_uint(a), bb = __float_as_uint(b);
    asm("prmt.b32 %0, %1, %2, 0x7632;" : "=r"(hi) : "r"(ab), "r"(bb));
    float ra = a - __uint_as_float(ab & 0xFFFF0000u);
    float rb = b - __uint_as_float(bb & 0xFFFF0000u);
    uint32_t rab = __float_as_uint(ra), rbb = __float_as_uint(rb);
    asm("prmt.b32 %0, %1, %2, 0x7632;" : "=r"(lo) : "r"(rab), "r"(rbb));
}
__device__ __forceinline__ float bf_lo(uint32_t v) {
    return __uint_as_float(v << 16);
}
__device__ __forceinline__ float bf_hi(uint32_t v) {
    return __uint_as_float(v & 0xFFFF0000u);
}
__device__ __forceinline__ uint32_t smem_u32(const void* p) {
    uint32_t a;
    asm("{ .reg .u64 t; cvta.to.shared.u64 t, %1; cvt.u32.u64 %0, t; }"
        : "=r"(a) : "l"(p));
    return a;
}
__device__ __forceinline__ void ldmA(uint32_t a[4], uint32_t addr) {
    asm volatile("ldmatrix.sync.aligned.m8n8.x4.shared.b16 {%0,%1,%2,%3}, [%4];"
                 : "=r"(a[0]), "=r"(a[1]), "=r"(a[2]), "=r"(a[3]) : "r"(addr));
}
__device__ __forceinline__ void mma16816(float d[4], const uint32_t a[4],
                                         uint32_t b0, uint32_t b1) {
    asm volatile(
        "mma.sync.aligned.m16n8k16.row.col.f32.bf16.bf16.f32 "
        "{%0,%1,%2,%3}, {%4,%5,%6,%7}, {%8,%9}, {%0,%1,%2,%3};"
        : "+f"(d[0]), "+f"(d[1]), "+f"(d[2]), "+f"(d[3])
        : "r"(a[0]), "r"(a[1]), "r"(a[2]), "r"(a[3]), "r"(b0), "r"(b1));
}

// prep: B fragments packed uint4 {bh0,bh1,bl0,bl1} per (m,kt,nt,lane).
// Weight split stays round-to-nearest (done once on the host side weights).
__global__ void prep_kernel(
    const float* __restrict__ w_xz, const float* __restrict__ w_hz,
    const float* __restrict__ w_xr, const float* __restrict__ w_hr,
    const float* __restrict__ w_c,  const float* __restrict__ w_u,
    const float* __restrict__ w_o,
    const float* __restrict__ b_xz, const float* __restrict__ b_hz,
    const float* __restrict__ b_xr, const float* __restrict__ b_hr,
    const float* __restrict__ b_c,  const float* __restrict__ b_u,
    const float* __restrict__ b_o)
{
    int m = blockIdx.x;                  // 0..6
    int t = threadIdx.x;                 // 0..1023
    int lane = t & 31;
    int reg  = (t >> 5) & 1;
    int nt   = (t >> 6) & 3;
    int kt   = (t >> 8) & 1;
    int term = (t >> 9) & 1;
    int g = lane >> 2, tig = lane & 3;
    const float* Wm = (m == 0) ? w_xz : (m == 1) ? w_hz : (m == 2) ? w_xr :
                      (m == 3) ? w_hr : (m == 4) ? w_c  : (m == 5) ? w_u : w_o;
    int n  = nt * 8 + g;
    int kk = kt * 16 + 2 * tig + reg * 8;
    float w0 = Wm[n * 32 + kk];
    float w1 = Wm[n * 32 + kk + 1];
    __nv_bfloat16 h0 = __float2bfloat16(w0);
    __nv_bfloat16 h1 = __float2bfloat16(w1);
    uint32_t val;
    if (term == 0) {
        val = (uint32_t)__bfloat16_as_ushort(h0) |
              ((uint32_t)__bfloat16_as_ushort(h1) << 16);
    } else {
        __nv_bfloat16 l0 = __float2bfloat16(w0 - __bfloat162float(h0));
        __nv_bfloat16 l1 = __float2bfloat16(w1 - __bfloat162float(h1));
        val = (uint32_t)__bfloat16_as_ushort(l0) |
              ((uint32_t)__bfloat16_as_ushort(l1) << 16);
    }
    g_wfrag[((((m * 2 + kt) * 4 + nt) * 32) + lane) * 4 + term * 2 + reg] = val;
    if (m == 0 && t < 32) {
        g_bias_stage[ 0 + t] = b_xz[t] + b_hz[t];
        g_bias_stage[32 + t] = b_xr[t] + b_hr[t];
        g_bias_stage[64 + t] = b_c[t]  + b_u[t];
        g_bias_stage[96 + t] = b_o[t];
    }
}

__global__ void __launch_bounds__(128, 4) gru_mma_kernel(
    const float* __restrict__ x, const float* __restrict__ h,
    float* __restrict__ out)
{
    extern __shared__ __align__(16) unsigned char dsm[];
    uint32_t* xs = (uint32_t*)dsm;                            // 36 u32 / row
    uint32_t* hs = (uint32_t*)(dsm + TILE_BYTES);
    uint32_t* ts = (uint32_t*)(dsm + 2 * TILE_BYTES);         // rv -> ht -> y
    const uint4* __restrict__ wfv = (const uint4*)g_wfrag;    // L1-resident

    const int tid = threadIdx.x;
    const int wid = tid >> 5, lane = tid & 31;
    const int g = lane >> 2, tig = lane & 3;
    const int wpx = wid * 32;
    const int l15 = lane & 15, lhi = lane >> 4;

    const uint32_t xs_a = smem_u32(xs);
    const uint32_t hs_a = smem_u32(hs);
    const uint32_t ts_a = smem_u32(ts);

    const int gp0 = blockIdx.x * 128;   // 4096 blocks cover 524288 px
    const int b   = gp0 >> 16;
    const int p0  = gp0 & 65535;
    const float* xb = x + (b * 32) * HW + p0 + tid;
    const float* hb = h + (b * 32) * HW + p0 + tid;

    // ---- load x,h (coalesced), split, fill tiles (row = own pixel) ----
#pragma unroll
    for (int j = 0; j < 16; j++) {
        float a0 = xb[(2 * j) * HW], a1 = xb[(2 * j + 1) * HW];
        float c0 = hb[(2 * j) * HW], c1 = hb[(2 * j + 1) * HW];
        uint32_t phi, plo;
        split2(a0, a1, phi, plo);
        xs[tid * 36 + j] = phi;  xs[tid * 36 + 16 + j] = plo;
        split2(c0, c1, phi, plo);
        hs[tid * 36 + j] = phi;  hs[tid * 36 + 16 + j] = plo;
    }
    __syncwarp();   // tiles are warp-local

#define LDFRAGS(base_a, ah, al, kt)                                            \
    {                                                                          \
        uint32_t ca = (uint32_t)(((kt) * 16 + lhi * 8) * 2);                   \
        _Pragma("unroll")                                                      \
        for (int mt = 0; mt < 2; mt++) {                                       \
            uint32_t rowb = (base_a) + (uint32_t)((wpx + mt * 16 + l15) * 144);\
            ldmA((ah)[mt], rowb + ca);                                         \
            ldmA((al)[mt], rowb + ca + 64);                                    \
        }                                                                      \
    }

#define BFRAG(m, kt, nt) __ldg(&wfv[(((m) * 2 + (kt)) * 4 + (nt)) * 32 + lane])

// One matrix, one kt: B fragments loaded ONCE into registers (4 uint4) and
// reused across all 3 split terms; MMAs issued term-major (dep distance 8).
#define MMA_MAT(d, m, kt, ah, al)                                              \
    {                                                                          \
        uint4 b0 = BFRAG(m, kt, 0), b1 = BFRAG(m, kt, 1);                      \
        uint4 b2 = BFRAG(m, kt, 2), b3 = BFRAG(m, kt, 3);                      \
        mma16816((d)[0][0], (ah)[0], b0.x, b0.y);                              \
        mma16816((d)[1][0], (ah)[1], b0.x, b0.y);                              \
        mma16816((d)[0][1], (ah)[0], b1.x, b1.y);                              \
        mma16816((d)[1][1], (ah)[1], b1.x, b1.y);                              \
        mma16816((d)[0][2], (ah)[0], b2.x, b2.y);                              \
        mma16816((d)[1][2], (ah)[1], b2.x, b2.y);                              \
        mma16816((d)[0][3], (ah)[0], b3.x, b3.y);                              \
        mma16816((d)[1][3], (ah)[1], b3.x, b3.y);                              \
        mma16816((d)[0][0], (al)[0], b0.x, b0.y);                              \
        mma16816((d)[1][0], (al)[1], b0.x, b0.y);                              \
        mma16816((d)[0][1], (al)[0], b1.x, b1.y);                              \
        mma16816((d)[1][1], (al)[1], b1.x, b1.y);                              \
        mma16816((d)[0][2], (al)[0], b2.x, b2.y);                              \
        mma16816((d)[1][2], (al)[1], b2.x, b2.y);                              \
        mma16816((d)[0][3], (al)[0], b3.x, b3.y);                              \
        mma16816((d)[1][3], (al)[1], b3.x, b3.y);                              \
        mma16816((d)[0][0], (ah)[0], b0.z, b0.w);                              \
        mma16816((d)[1][0], (ah)[1], b0.z, b0.w);                              \
        mma16816((d)[0][1], (ah)[0], b1.z, b1.w);                              \
        mma16816((d)[1][1], (ah)[1], b1.z, b1.w);                              \
        mma16816((d)[0][2], (ah)[0], b2.z, b2.w);                              \
        mma16816((d)[1][2], (ah)[1], b2.z, b2.w);                              \
        mma16816((d)[0][3], (ah)[0], b3.z, b3.w);                              \
        mma16816((d)[1][3], (ah)[1], b3.z, b3.w);                              \
    }

    // ---- phase 1: z_pre, r_pre only (64 accumulators live) ----
    float dz[2][4][4] = {}, dr[2][4][4] = {};
#pragma unroll
    for (int kt = 0; kt < 2; kt++) {
        uint32_t ah[2][4], al[2][4];
        LDFRAGS(xs_a, ah, al, kt)
        MMA_MAT(dz, 0, kt, ah, al)
        MMA_MAT(dr, 2, kt, ah, al)
        LDFRAGS(hs_a, ah, al, kt)
        MMA_MAT(dz, 1, kt, ah, al)
        MMA_MAT(dr, 3, kt, ah, al)
    }

    // z = sigmoid(z_pre + bz) kept in dz; rv = sigmoid(r_pre + br) * h -> ts
#pragma unroll
    for (int mt = 0; mt < 2; mt++)
#pragma unroll
        for (int nt = 0; nt < 4; nt++) {
            const int ch0 = nt * 8 + 2 * tig;
            const float bz0 = cBias[ch0], bz1 = cBias[ch0 + 1];
            const float br0 = cBias[32 + ch0], br1 = cBias[32 + ch0 + 1];
#pragma unroll
            for (int hf = 0; hf < 2; hf++) {
                int px = wpx + mt * 16 + g + hf * 8;
                int wb = px * 36 + nt * 4 + tig;
                uint32_t hh = hs[wb], hl = hs[wb + 16];
                float h0 = bf_lo(hh) + bf_lo(hl);
                float h1 = bf_hi(hh) + bf_hi(hl);
                dz[mt][nt][hf * 2 + 0] = sigmoidf_(dz[mt][nt][hf * 2 + 0] + bz0);
                dz[mt][nt][hf * 2 + 1] = sigmoidf_(dz[mt][nt][hf * 2 + 1] + bz1);
                float r0 = sigmoidf_(dr[mt][nt][hf * 2 + 0] + br0) * h0;
                float r1 = sigmoidf_(dr[mt][nt][hf * 2 + 1] + br1) * h1;
                uint32_t phi, plo;
                split2(r0, r1, phi, plo);
                ts[wb] = phi;  ts[wb + 16] = plo;
            }
        }
    __syncwarp();

    // ---- phase 2: dc = Wc*x + Wu*rv  (xs intact, rv in ts) ----
    float dc[2][4][4] = {};
#pragma unroll
    for (int kt = 0; kt < 2; kt++) {
        uint32_t ah[2][4], al[2][4];
        LDFRAGS(xs_a, ah, al, kt)
        MMA_MAT(dc, 4, kt, ah, al)
        LDFRAGS(ts_a, ah, al, kt)
        MMA_MAT(dc, 5, kt, ah, al)
    }
    __syncwarp();   // rv reads done before ts overwrite

    // blend: h_t = h + z*(tanh(c_pre+bc) - h) -> ts (bf16 split)
#pragma unroll
    for (int mt = 0; mt < 2; mt++)
#pragma unroll
        for (int nt = 0; nt < 4; nt++) {
            const int ch0 = nt * 8 + 2 * tig;
            const float bc0 = cBias[64 + ch0], bc1 = cBias[64 + ch0 + 1];
#pragma unroll
            for (int hf = 0; hf < 2; hf++) {
                int px = wpx + mt * 16 + g + hf * 8;
                int wb = px * 36 + nt * 4 + tig;
                uint32_t hh = hs[wb], hl = hs[wb + 16];
                float h0 = bf_lo(hh) + bf_lo(hl);
                float h1 = bf_hi(hh) + bf_hi(hl);
                float c0 = tanhf_(dc[mt][nt][hf * 2 + 0] + bc0);
                float c1 = tanhf_(dc[mt][nt][hf * 2 + 1] + bc1);
                float t0 = fmaf(dz[mt][nt][hf * 2 + 0], c0 - h0, h0);
                float t1 = fmaf(dz[mt][nt][hf * 2 + 1], c1 - h1, h1);
                uint32_t phi, plo;
                split2(t0, t1, phi, plo);
                ts[wb] = phi;  ts[wb + 16] = plo;
            }
        }
    __syncwarp();

    // coalesced h_t store: thread reads its own pixel row from ts
    {
        float* houtb = out + NB * 32 * HW + (b * 32) * HW + p0 + tid;
#pragma unroll
        for (int w = 0; w < 16; w++) {
            int ch0 = (w >> 2) * 8 + 2 * (w & 3);
            uint32_t hh = ts[tid * 36 + w], hl = ts[tid * 36 + 16 + w];
            houtb[ch0 * HW]       = bf_lo(hh) + bf_lo(hl);
            houtb[(ch0 + 1) * HW] = bf_hi(hh) + bf_hi(hl);
        }
    }

    // ---- phase 3: y = Wo * h_t + by  (h_t in ts) ----
    float dy[2][4][4] = {};
#pragma unroll
    for (int kt = 0; kt < 2; kt++) {
        uint32_t ah[2][4], al[2][4];
        LDFRAGS(ts_a, ah, al, kt)
        MMA_MAT(dy, 6, kt, ah, al)
    }
    __syncwarp();   // ht reads done before y overwrite

    // y + bias -> ts (bf16 split), then coalesced row store
#pragma unroll
    for (int mt = 0; mt < 2; mt++)
#pragma unroll
        for (int nt = 0; nt < 4; nt++) {
            const int ch0 = nt * 8 + 2 * tig;
            const float by0 = cBias[96 + ch0], by1 = cBias[96 + ch0 + 1];
#pragma unroll
            for (int hf = 0; hf < 2; hf++) {
                int px = wpx + mt * 16 + g + hf * 8;
                int wb = px * 36 + nt * 4 + tig;
                uint32_t phi, plo;
                split2(dy[mt][nt][hf * 2 + 0] + by0,
                       dy[mt][nt][hf * 2 + 1] + by1, phi, plo);
                ts[wb] = phi;  ts[wb + 16] = plo;
            }
        }
    __syncwarp();

    {
        float* youtb = out + (b * 32) * HW + p0 + tid;
#pragma unroll
        for (int w = 0; w < 16; w++) {
            int ch0 = (w >> 2) * 8 + 2 * (w & 3);
            uint32_t yh = ts[tid * 36 + w], yl = ts[tid * 36 + 16 + w];
            youtb[ch0 * HW]       = bf_lo(yh) + bf_lo(yl);
            youtb[(ch0 + 1) * HW] = bf_hi(yh) + bf_hi(yl);
        }
    }
}

extern "C" void kernel_launch(void* const* d_in, const int* in_sizes, int n_in,
                              void* d_out, int out_size) {
    const float* x    = (const float*)d_in[0];
    const float* h    = (const float*)d_in[1];
    const float* w_xz = (const float*)d_in[2];
    const float* b_xz = (const float*)d_in[3];
    const float* w_hz = (const float*)d_in[4];
    const float* b_hz = (const float*)d_in[5];
    const float* w_xr = (const float*)d_in[6];
    const float* b_xr = (const float*)d_in[7];
    const float* w_hr = (const float*)d_in[8];
    const float* b_hr = (const float*)d_in[9];
    const float* w_c  = (const float*)d_in[10];
    const float* b_c  = (const float*)d_in[11];
    const float* w_u  = (const float*)d_in[12];
    const float* b_u  = (const float*)d_in[13];
    const float* w_o  = (const float*)d_in[14];
    const float* b_o  = (const float*)d_in[15];
    float* out = (float*)d_out;

    prep_kernel<<<7, 1024>>>(w_xz, w_hz, w_xr, w_hr, w_c, w_u, w_o,
                             b_xz, b_hz, b_xr, b_hr, b_c, b_u, b_o);

    void *csym = nullptr, *gsym = nullptr;
    cudaGetSymbolAddress(&csym, cBias);
    cudaGetSymbolAddress(&gsym, g_bias_stage);
    cudaMemcpyAsync(csym, gsym, sizeof(float) * 128, cudaMemcpyDeviceToDevice);

    cudaFuncSetAttribute(gru_mma_kernel,
                         cudaFuncAttributeMaxDynamicSharedMemorySize, SMEM_TOTAL);
    gru_mma_kernel<<<4096, 128, SMEM_TOTAL>>>(x, h, out);
}

// round 15
// speedup vs baseline: 1.5567x; 1.0061x over previous
#include <cuda_runtime.h>
#include <cuda_bf16.h>
#include <cstdint>

// ConvGRUCell via warp-level mma.sync (HMMA bf16, f32 accum), compute_103-safe.
// fp32 accuracy via bf16 hi/lo split (3 terms: Ah*Wh + Al*Wh + Ah*Wl).
// R15: the three bank-conflicted scalar smem access groups (tile fill STS.32,
// h_t/y row readback LDS.32 -- bank = 4*tid+j, 4-way) are vectorized to
// 128-bit accesses, which on the 36-word (9x16B) row stride rotate
// super-banks by tid%8 and run conflict-free at the 4-wavefront minimum.
// ~-384 L1 wavefronts/warp (~30% of L1 traffic, the binding pipe in R14).

#define HW 65536        // 256*256
#define NB 8

#define TILE_BYTES 18432
#define SMEM_TOTAL (3 * TILE_BYTES)     // 55296 B -> 4 CTAs/SM

__device__ __align__(16) uint32_t g_wfrag[7168];
__device__ float g_bias_stage[128];
__constant__ float cBias[128];   // [bz | br | bc | by]

__device__ __forceinline__ float sigmoidf_(float a) {
    a = fminf(fmaxf(a, -30.f), 30.f);
    float e = __expf(-a);
    return __fdividef(1.f, 1.f + e);
}
__device__ __forceinline__ float tanhf_(float a) {
    a = fminf(fmaxf(a, -15.f), 15.f);
    float e = __expf(-2.f * a);
    return (1.f - e) * __fdividef(1.f, 1.f + e);
}
// bit-trick bf16x2 split: hi = {trunc_bf16(b), trunc_bf16(a)},
// lo captures the residual exactly -> pair error ~2^-16.
__device__ __forceinline__ void split2(float a, float b, uint32_t& hi, uint32_t& lo) {
    uint32_t ab = __float_as_uint(a), bb = __float_as_uint(b);
    asm("prmt.b32 %0, %1, %2, 0x7632;" : "=r"(hi) : "r"(ab), "r"(bb));
    float ra = a - __uint_as_float(ab & 0xFFFF0000u);
    float rb = b - __uint_as_float(bb & 0xFFFF0000u);
    uint32_t rab = __float_as_uint(ra), rbb = __float_as_uint(rb);
    asm("prmt.b32 %0, %1, %2, 0x7632;" : "=r"(lo) : "r"(rab), "r"(rbb));
}
__device__ __forceinline__ float bf_lo(uint32_t v) {
    return __uint_as_float(v << 16);
}
__device__ __forceinline__ float bf_hi(uint32_t v) {
    return __uint_as_float(v & 0xFFFF0000u);
}
__device__ __forceinline__ uint32_t smem_u32(const void* p) {
    uint32_t a;
    asm("{ .reg .u64 t; cvta.to.shared.u64 t, %1; cvt.u32.u64 %0, t; }"
        : "=r"(a) : "l"(p));
    return a;
}
__device__ __forceinline__ void ldmA(uint32_t a[4], uint32_t addr) {
    asm volatile("ldmatrix.sync.aligned.m8n8.x4.shared.b16 {%0,%1,%2,%3}, [%4];"
                 : "=r"(a[0]), "=r"(a[1]), "=r"(a[2]), "=r"(a[3]) : "r"(addr));
}
__device__ __forceinline__ void mma16816(float d[4], const uint32_t a[4],
                                         uint32_t b0, uint32_t b1) {
    asm volatile(
        "mma.sync.aligned.m16n8k16.row.col.f32.bf16.bf16.f32 "
        "{%0,%1,%2,%3}, {%4,%5,%6,%7}, {%8,%9}, {%0,%1,%2,%3};"
        : "+f"(d[0]), "+f"(d[1]), "+f"(d[2]), "+f"(d[3])
        : "r"(a[0]), "r"(a[1]), "r"(a[2]), "r"(a[3]), "r"(b0), "r"(b1));
}

// prep: B fragments packed uint4 {bh0,bh1,bl0,bl1} per (m,kt,nt,lane).
__global__ void prep_kernel(
    const float* __restrict__ w_xz, const float* __restrict__ w_hz,
    const float* __restrict__ w_xr, const float* __restrict__ w_hr,
    const float* __restrict__ w_c,  const float* __restrict__ w_u,
    const float* __restrict__ w_o,
    const float* __restrict__ b_xz, const float* __restrict__ b_hz,
    const float* __restrict__ b_xr, const float* __restrict__ b_hr,
    const float* __restrict__ b_c,  const float* __restrict__ b_u,
    const float* __restrict__ b_o)
{
    int m = blockIdx.x;                  // 0..6
    int t = threadIdx.x;                 // 0..1023
    int lane = t & 31;
    int reg  = (t >> 5) & 1;
    int nt   = (t >> 6) & 3;
    int kt   = (t >> 8) & 1;
    int term = (t >> 9) & 1;
    int g = lane >> 2, tig = lane & 3;
    const float* Wm = (m == 0) ? w_xz : (m == 1) ? w_hz : (m == 2) ? w_xr :
                      (m == 3) ? w_hr : (m == 4) ? w_c  : (m == 5) ? w_u : w_o;
    int n  = nt * 8 + g;
    int kk = kt * 16 + 2 * tig + reg * 8;
    float w0 = Wm[n * 32 + kk];
    float w1 = Wm[n * 32 + kk + 1];
    __nv_bfloat16 h0 = __float2bfloat16(w0);
    __nv_bfloat16 h1 = __float2bfloat16(w1);
    uint32_t val;
    if (term == 0) {
        val = (uint32_t)__bfloat16_as_ushort(h0) |
              ((uint32_t)__bfloat16_as_ushort(h1) << 16);
    } else {
        __nv_bfloat16 l0 = __float2bfloat16(w0 - __bfloat162float(h0));
        __nv_bfloat16 l1 = __float2bfloat16(w1 - __bfloat162float(h1));
        val = (uint32_t)__bfloat16_as_ushort(l0) |
              ((uint32_t)__bfloat16_as_ushort(l1) << 16);
    }
    g_wfrag[((((m * 2 + kt) * 4 + nt) * 32) + lane) * 4 + term * 2 + reg] = val;
    if (m == 0 && t < 32) {
        g_bias_stage[ 0 + t] = b_xz[t] + b_hz[t];
        g_bias_stage[32 + t] = b_xr[t] + b_hr[t];
        g_bias_stage[64 + t] = b_c[t]  + b_u[t];
        g_bias_stage[96 + t] = b_o[t];
    }
}

__global__ void __launch_bounds__(128, 4) gru_mma_kernel(
    const float* __restrict__ x, const float* __restrict__ h,
    float* __restrict__ out)
{
    extern __shared__ __align__(16) unsigned char dsm[];
    uint32_t* xs = (uint32_t*)dsm;                            // 36 u32 / row
    uint32_t* hs = (uint32_t*)(dsm + TILE_BYTES);
    uint32_t* ts = (uint32_t*)(dsm + 2 * TILE_BYTES);         // rv -> ht -> y
    const uint4* __restrict__ wfv = (const uint4*)g_wfrag;    // L1-resident

    const int tid = threadIdx.x;
    const int wid = tid >> 5, lane = tid & 31;
    const int g = lane >> 2, tig = lane & 3;
    const int wpx = wid * 32;
    const int l15 = lane & 15, lhi = lane >> 4;

    const uint32_t xs_a = smem_u32(xs);
    const uint32_t hs_a = smem_u32(hs);
    const uint32_t ts_a = smem_u32(ts);

    const int gp0 = blockIdx.x * 128;   // 4096 blocks cover 524288 px
    const int b   = gp0 >> 16;
    const int p0  = gp0 & 65535;
    const float* xb = x + (b * 32) * HW + p0 + tid;
    const float* hb = h + (b * 32) * HW + p0 + tid;

    // ---- load x,h, split, fill tiles via conflict-free STS.128 ----
    {
        uint32_t fxh[4], fxl[4], fhh[4], fhl[4];
#pragma unroll
        for (int j = 0; j < 16; j++) {
            float a0 = xb[(2 * j) * HW], a1 = xb[(2 * j + 1) * HW];
            float c0 = hb[(2 * j) * HW], c1 = hb[(2 * j + 1) * HW];
            int e = j & 3;
            split2(a0, a1, fxh[e], fxl[e]);
            split2(c0, c1, fhh[e], fhl[e]);
            if (e == 3) {
                int c = (j >> 2) * 4;
                *(uint4*)&xs[tid * 36 + c]      = make_uint4(fxh[0], fxh[1], fxh[2], fxh[3]);
                *(uint4*)&xs[tid * 36 + 16 + c] = make_uint4(fxl[0], fxl[1], fxl[2], fxl[3]);
                *(uint4*)&hs[tid * 36 + c]      = make_uint4(fhh[0], fhh[1], fhh[2], fhh[3]);
                *(uint4*)&hs[tid * 36 + 16 + c] = make_uint4(fhl[0], fhl[1], fhl[2], fhl[3]);
            }
        }
    }
    __syncwarp();   // tiles are warp-local

#define LDFRAGS(base_a, ah, al, kt)                                            \
    {                                                                          \
        uint32_t ca = (uint32_t)(((kt) * 16 + lhi * 8) * 2);                   \
        _Pragma("unroll")                                                      \
        for (int mt = 0; mt < 2; mt++) {                                       \
            uint32_t rowb = (base_a) + (uint32_t)((wpx + mt * 16 + l15) * 144);\
            ldmA((ah)[mt], rowb + ca);                                         \
            ldmA((al)[mt], rowb + ca + 64);                                    \
        }                                                                      \
    }

#define BFRAG(m, kt, nt) __ldg(&wfv[(((m) * 2 + (kt)) * 4 + (nt)) * 32 + lane])

// One matrix, one kt: B fragments loaded ONCE (4 uint4) and reused across all
// 3 split terms; MMAs term-major (dep distance 8).
#define MMA_MAT(d, m, kt, ah, al)                                              \
    {                                                                          \
        uint4 b0 = BFRAG(m, kt, 0), b1 = BFRAG(m, kt, 1);                      \
        uint4 b2 = BFRAG(m, kt, 2), b3 = BFRAG(m, kt, 3);                      \
        mma16816((d)[0][0], (ah)[0], b0.x, b0.y);                              \
        mma16816((d)[1][0], (ah)[1], b0.x, b0.y);                              \
        mma16816((d)[0][1], (ah)[0], b1.x, b1.y);                              \
        mma16816((d)[1][1], (ah)[1], b1.x, b1.y);                              \
        mma16816((d)[0][2], (ah)[0], b2.x, b2.y);                              \
        mma16816((d)[1][2], (ah)[1], b2.x, b2.y);                              \
        mma16816((d)[0][3], (ah)[0], b3.x, b3.y);                              \
        mma16816((d)[1][3], (ah)[1], b3.x, b3.y);                              \
        mma16816((d)[0][0], (al)[0], b0.x, b0.y);                              \
        mma16816((d)[1][0], (al)[1], b0.x, b0.y);                              \
        mma16816((d)[0][1], (al)[0], b1.x, b1.y);                              \
        mma16816((d)[1][1], (al)[1], b1.x, b1.y);                              \
        mma16816((d)[0][2], (al)[0], b2.x, b2.y);                              \
        mma16816((d)[1][2], (al)[1], b2.x, b2.y);                              \
        mma16816((d)[0][3], (al)[0], b3.x, b3.y);                              \
        mma16816((d)[1][3], (al)[1], b3.x, b3.y);                              \
        mma16816((d)[0][0], (ah)[0], b0.z, b0.w);                              \
        mma16816((d)[1][0], (ah)[1], b0.z, b0.w);                              \
        mma16816((d)[0][1], (ah)[0], b1.z, b1.w);                              \
        mma16816((d)[1][1], (ah)[1], b1.z, b1.w);                              \
        mma16816((d)[0][2], (ah)[0], b2.z, b2.w);                              \
        mma16816((d)[1][2], (ah)[1], b2.z, b2.w);                              \
        mma16816((d)[0][3], (ah)[0], b3.z, b3.w);                              \
        mma16816((d)[1][3], (ah)[1], b3.z, b3.w);                              \
    }

    // ---- phase 1: z_pre, r_pre only (64 accumulators live) ----
    float dz[2][4][4] = {}, dr[2][4][4] = {};
#pragma unroll
    for (int kt = 0; kt < 2; kt++) {
        uint32_t ah[2][4], al[2][4];
        LDFRAGS(xs_a, ah, al, kt)
        MMA_MAT(dz, 0, kt, ah, al)
        MMA_MAT(dr, 2, kt, ah, al)
        LDFRAGS(hs_a, ah, al, kt)
        MMA_MAT(dz, 1, kt, ah, al)
        MMA_MAT(dr, 3, kt, ah, al)
    }

    // z = sigmoid(z_pre + bz) kept in dz; rv = sigmoid(r_pre + br) * h -> ts
    // (scalar LDS/STS here are conflict-free: bank = 4(px+nt)+tig)
#pragma unroll
    for (int mt = 0; mt < 2; mt++)
#pragma unroll
        for (int nt = 0; nt < 4; nt++) {
            const int ch0 = nt * 8 + 2 * tig;
            const float bz0 = cBias[ch0], bz1 = cBias[ch0 + 1];
            const float br0 = cBias[32 + ch0], br1 = cBias[32 + ch0 + 1];
#pragma unroll
            for (int hf = 0; hf < 2; hf++) {
                int px = wpx + mt * 16 + g + hf * 8;
                int wb = px * 36 + nt * 4 + tig;
                uint32_t hh = hs[wb], hl = hs[wb + 16];
                float h0 = bf_lo(hh) + bf_lo(hl);
                float h1 = bf_hi(hh) + bf_hi(hl);
                dz[mt][nt][hf * 2 + 0] = sigmoidf_(dz[mt][nt][hf * 2 + 0] + bz0);
                dz[mt][nt][hf * 2 + 1] = sigmoidf_(dz[mt][nt][hf * 2 + 1] + bz1);
                float r0 = sigmoidf_(dr[mt][nt][hf * 2 + 0] + br0) * h0;
                float r1 = sigmoidf_(dr[mt][nt][hf * 2 + 1] + br1) * h1;
                uint32_t phi, plo;
                split2(r0, r1, phi, plo);
                ts[wb] = phi;  ts[wb + 16] = plo;
            }
        }
    __syncwarp();

    // ---- phase 2: dc = Wc*x + Wu*rv  (xs intact, rv in ts) ----
    float dc[2][4][4] = {};
#pragma unroll
    for (int kt = 0; kt < 2; kt++) {
        uint32_t ah[2][4], al[2][4];
        LDFRAGS(xs_a, ah, al, kt)
        MMA_MAT(dc, 4, kt, ah, al)
        LDFRAGS(ts_a, ah, al, kt)
        MMA_MAT(dc, 5, kt, ah, al)
    }
    __syncwarp();   // rv reads done before ts overwrite

    // blend: h_t = h + z*(tanh(c_pre+bc) - h) -> ts (bf16 split)
#pragma unroll
    for (int mt = 0; mt < 2; mt++)
#pragma unroll
        for (int nt = 0; nt < 4; nt++) {
            const int ch0 = nt * 8 + 2 * tig;
            const float bc0 = cBias[64 + ch0], bc1 = cBias[64 + ch0 + 1];
#pragma unroll
            for (int hf = 0; hf < 2; hf++) {
                int px = wpx + mt * 16 + g + hf * 8;
                int wb = px * 36 + nt * 4 + tig;
                uint32_t hh = hs[wb], hl = hs[wb + 16];
                float h0 = bf_lo(hh) + bf_lo(hl);
                float h1 = bf_hi(hh) + bf_hi(hl);
                float c0 = tanhf_(dc[mt][nt][hf * 2 + 0] + bc0);
                float c1 = tanhf_(dc[mt][nt][hf * 2 + 1] + bc1);
                float t0 = fmaf(dz[mt][nt][hf * 2 + 0], c0 - h0, h0);
                float t1 = fmaf(dz[mt][nt][hf * 2 + 1], c1 - h1, h1);
                uint32_t phi, plo;
                split2(t0, t1, phi, plo);
                ts[wb] = phi;  ts[wb + 16] = plo;
            }
        }
    __syncwarp();

    // coalesced h_t store: vectorized row readback (conflict-free LDS.128)
    {
        float* houtb = out + NB * 32 * HW + (b * 32) * HW + p0 + tid;
#pragma unroll
        for (int c = 0; c < 4; c++) {
            uint4 H = *(const uint4*)&ts[tid * 36 + c * 4];
            uint4 L = *(const uint4*)&ts[tid * 36 + 16 + c * 4];
            int ch0 = c * 8;
            houtb[(ch0 + 0) * HW] = bf_lo(H.x) + bf_lo(L.x);
            houtb[(ch0 + 1) * HW] = bf_hi(H.x) + bf_hi(L.x);
            houtb[(ch0 + 2) * HW] = bf_lo(H.y) + bf_lo(L.y);
            houtb[(ch0 + 3) * HW] = bf_hi(H.y) + bf_hi(L.y);
            houtb[(ch0 + 4) * HW] = bf_lo(H.z) + bf_lo(L.z);
            houtb[(ch0 + 5) * HW] = bf_hi(H.z) + bf_hi(L.z);
            houtb[(ch0 + 6) * HW] = bf_lo(H.w) + bf_lo(L.w);
            houtb[(ch0 + 7) * HW] = bf_hi(H.w) + bf_hi(L.w);
        }
    }

    // ---- phase 3: y = Wo * h_t + by  (h_t in ts) ----
    float dy[2][4][4] = {};
#pragma unroll
    for (int kt = 0; kt < 2; kt++) {
        uint32_t ah[2][4], al[2][4];
        LDFRAGS(ts_a, ah, al, kt)
        MMA_MAT(dy, 6, kt, ah, al)
    }
    __syncwarp();   // ht reads done before y overwrite

    // y + bias -> ts (bf16 split; conflict-free scalar STS)
#pragma unroll
    for (int mt = 0; mt < 2; mt++)
#pragma unroll
        for (int nt = 0; nt < 4; nt++) {
            const int ch0 = nt * 8 + 2 * tig;
            const float by0 = cBias[96 + ch0], by1 = cBias[96 + ch0 + 1];
#pragma unroll
            for (int hf = 0; hf < 2; hf++) {
                int px = wpx + mt * 16 + g + hf * 8;
                int wb = px * 36 + nt * 4 + tig;
                uint32_t phi, plo;
                split2(dy[mt][nt][hf * 2 + 0] + by0,
                       dy[mt][nt][hf * 2 + 1] + by1, phi, plo);
                ts[wb] = phi;  ts[wb + 16] = plo;
            }
        }
    __syncwarp();

    // coalesced y store: vectorized row readback
    {
        float* youtb = out + (b * 32) * HW + p0 + tid;
#pragma unroll
        for (int c = 0; c < 4; c++) {
            uint4 H = *(const uint4*)&ts[tid * 36 + c * 4];
            uint4 L = *(const uint4*)&ts[tid * 36 + 16 + c * 4];
            int ch0 = c * 8;
            youtb[(ch0 + 0) * HW] = bf_lo(H.x) + bf_lo(L.x);
            youtb[(ch0 + 1) * HW] = bf_hi(H.x) + bf_hi(L.x);
            youtb[(ch0 + 2) * HW] = bf_lo(H.y) + bf_lo(L.y);
            youtb[(ch0 + 3) * HW] = bf_hi(H.y) + bf_hi(L.y);
            youtb[(ch0 + 4) * HW] = bf_lo(H.z) + bf_lo(L.z);
            youtb[(ch0 + 5) * HW] = bf_hi(H.z) + bf_hi(L.z);
            youtb[(ch0 + 6) * HW] = bf_lo(H.w) + bf_lo(L.w);
            youtb[(ch0 + 7) * HW] = bf_hi(H.w) + bf_hi(L.w);
        }
    }
}

extern "C" void kernel_launch(void* const* d_in, const int* in_sizes, int n_in,
                              void* d_out, int out_size) {
    const float* x    = (const float*)d_in[0];
    const float* h    = (const float*)d_in[1];
    const float* w_xz = (const float*)d_in[2];
    const float* b_xz = (const float*)d_in[3];
    const float* w_hz = (const float*)d_in[4];
    const float* b_hz = (const float*)d_in[5];
    const float* w_xr = (const float*)d_in[6];
    const float* b_xr = (const float*)d_in[7];
    const float* w_hr = (const float*)d_in[8];
    const float* b_hr = (const float*)d_in[9];
    const float* w_c  = (const float*)d_in[10];
    const float* b_c  = (const float*)d_in[11];
    const float* w_u  = (const float*)d_in[12];
    const float* b_u  = (const float*)d_in[13];
    const float* w_o  = (const float*)d_in[14];
    const float* b_o  = (const float*)d_in[15];
    float* out = (float*)d_out;

    prep_kernel<<<7, 1024>>>(w_xz, w_hz, w_xr, w_hr, w_c, w_u, w_o,
                             b_xz, b_hz, b_xr, b_hr, b_c, b_u, b_o);

    void *csym = nullptr, *gsym = nullptr;
    cudaGetSymbolAddress(&csym, cBias);
    cudaGetSymbolAddress(&gsym, g_bias_stage);
    cudaMemcpyAsync(csym, gsym, sizeof(float) * 128, cudaMemcpyDeviceToDevice);

    cudaFuncSetAttribute(gru_mma_kernel,
                         cudaFuncAttributeMaxDynamicSharedMemorySize, SMEM_TOTAL);
    gru_mma_kernel<<<4096, 128, SMEM_TOTAL>>>(x, h, out);
}

// round 16
// speedup vs baseline: 1.7266x; 1.1091x over previous
#include <cuda_runtime.h>
#include <cuda_fp16.h>
#include <cstdint>

// ConvGRUCell via warp-level mma.sync (HMMA fp16, f32 accum), compute_103-safe.
// R16: fp16 instead of bf16. fp16's 11 mantissa bits let the split drop from
// 3 terms to 2 (Ah*Wh + Al*Wh, weights single RN fp16): MMAs 336 -> 224 per
// warp, B fragments halve to uint2 (LDG.64). Weight-quant error 2^-12 ->
// predicted rel_err ~1.5e-4 (gate 1e-3).
//
// Block = 128 threads = 4 warps; warp w owns pixels [32w,32w+32); tiles are
// warp-local (only __syncwarp). 3 tiles x 18.4KB = 55.3KB -> 4 CTAs/SM.

#define HW 65536        // 256*256
#define NB 8

#define TILE_BYTES 18432
#define SMEM_TOTAL (3 * TILE_BYTES)

__device__ __align__(16) uint32_t g_wfrag[3584];   // uint2 pairs {b0,b1}
__device__ float g_bias_stage[128];
__constant__ float cBias[128];   // [bz | br | bc | by]

__device__ __forceinline__ float sigmoidf_(float a) {
    a = fminf(fmaxf(a, -30.f), 30.f);
    float e = __expf(-a);
    return __fdividef(1.f, 1.f + e);
}
__device__ __forceinline__ float tanhf_(float a) {
    a = fminf(fmaxf(a, -15.f), 15.f);
    float e = __expf(-2.f * a);
    return (1.f - e) * __fdividef(1.f, 1.f + e);
}
// fp16x2 split: hi = {f16(a), f16(b)} (RN), lo = exact residuals in f16.
__device__ __forceinline__ void split2(float a, float b, uint32_t& hi, uint32_t& lo) {
    __half2 hp = __floats2half2_rn(a, b);        // .x=a (low 16), .y=b
    float2 back = __half22float2(hp);
    __half2 lp = __floats2half2_rn(a - back.x, b - back.y);
    hi = *(uint32_t*)&hp;
    lo = *(uint32_t*)&lp;
}
__device__ __forceinline__ float2 up2(uint32_t v) {
    return __half22float2(*(__half2*)&v);
}
__device__ __forceinline__ uint32_t smem_u32(const void* p) {
    uint32_t a;
    asm("{ .reg .u64 t; cvta.to.shared.u64 t, %1; cvt.u32.u64 %0, t; }"
        : "=r"(a) : "l"(p));
    return a;
}
__device__ __forceinline__ void ldmA(uint32_t a[4], uint32_t addr) {
    asm volatile("ldmatrix.sync.aligned.m8n8.x4.shared.b16 {%0,%1,%2,%3}, [%4];"
                 : "=r"(a[0]), "=r"(a[1]), "=r"(a[2]), "=r"(a[3]) : "r"(addr));
}
__device__ __forceinline__ void mma16816(float d[4], const uint32_t a[4],
                                         uint32_t b0, uint32_t b1) {
    asm volatile(
        "mma.sync.aligned.m16n8k16.row.col.f32.f16.f16.f32 "
        "{%0,%1,%2,%3}, {%4,%5,%6,%7}, {%8,%9}, {%0,%1,%2,%3};"
        : "+f"(d[0]), "+f"(d[1]), "+f"(d[2]), "+f"(d[3])
        : "r"(a[0]), "r"(a[1]), "r"(a[2]), "r"(a[3]), "r"(b0), "r"(b1));
}

// prep: fp16 B fragments, uint2 {b0,b1} per (m,kt,nt,lane).
__global__ void prep_kernel(
    const float* __restrict__ w_xz, const float* __restrict__ w_hz,
    const float* __restrict__ w_xr, const float* __restrict__ w_hr,
    const float* __restrict__ w_c,  const float* __restrict__ w_u,
    const float* __restrict__ w_o,
    const float* __restrict__ b_xz, const float* __restrict__ b_hz,
    const float* __restrict__ b_xr, const float* __restrict__ b_hr,
    const float* __restrict__ b_c,  const float* __restrict__ b_u,
    const float* __restrict__ b_o)
{
    int m = blockIdx.x;                  // 0..6
    int t = threadIdx.x;                 // 0..511
    int lane = t & 31;
    int reg  = (t >> 5) & 1;
    int nt   = (t >> 6) & 3;
    int kt   = (t >> 8) & 1;
    int g = lane >> 2, tig = lane & 3;
    const float* Wm = (m == 0) ? w_xz : (m == 1) ? w_hz : (m == 2) ? w_xr :
                      (m == 3) ? w_hr : (m == 4) ? w_c  : (m == 5) ? w_u : w_o;
    int n  = nt * 8 + g;
    int kk = kt * 16 + 2 * tig + reg * 8;
    __half2 hp = __floats2half2_rn(Wm[n * 32 + kk], Wm[n * 32 + kk + 1]);
    g_wfrag[((((m * 2 + kt) * 4 + nt) * 32) + lane) * 2 + reg] = *(uint32_t*)&hp;
    if (m == 0 && t < 32) {
        g_bias_stage[ 0 + t] = b_xz[t] + b_hz[t];
        g_bias_stage[32 + t] = b_xr[t] + b_hr[t];
        g_bias_stage[64 + t] = b_c[t]  + b_u[t];
        g_bias_stage[96 + t] = b_o[t];
    }
}

__global__ void __launch_bounds__(128, 4) gru_mma_kernel(
    const float* __restrict__ x, const float* __restrict__ h,
    float* __restrict__ out)
{
    extern __shared__ __align__(16) unsigned char dsm[];
    uint32_t* xs = (uint32_t*)dsm;                            // 36 u32 / row
    uint32_t* hs = (uint32_t*)(dsm + TILE_BYTES);
    uint32_t* ts = (uint32_t*)(dsm + 2 * TILE_BYTES);         // rv -> ht -> y
    const uint2* __restrict__ wfv = (const uint2*)g_wfrag;    // L1-resident

    const int tid = threadIdx.x;
    const int wid = tid >> 5, lane = tid & 31;
    const int g = lane >> 2, tig = lane & 3;
    const int wpx = wid * 32;
    const int l15 = lane & 15, lhi = lane >> 4;

    const uint32_t xs_a = smem_u32(xs);
    const uint32_t hs_a = smem_u32(hs);
    const uint32_t ts_a = smem_u32(ts);

    const int gp0 = blockIdx.x * 128;   // 4096 blocks cover 524288 px
    const int b   = gp0 >> 16;
    const int p0  = gp0 & 65535;
    const float* xb = x + (b * 32) * HW + p0 + tid;
    const float* hb = h + (b * 32) * HW + p0 + tid;

    // ---- load x,h, split to fp16 hi/lo, fill tiles (row = own pixel) ----
    {
        uint32_t fxh[4], fxl[4], fhh[4], fhl[4];
#pragma unroll
        for (int j = 0; j < 16; j++) {
            float a0 = xb[(2 * j) * HW], a1 = xb[(2 * j + 1) * HW];
            float c0 = hb[(2 * j) * HW], c1 = hb[(2 * j + 1) * HW];
            int e = j & 3;
            split2(a0, a1, fxh[e], fxl[e]);
            split2(c0, c1, fhh[e], fhl[e]);
            if (e == 3) {
                int c = (j >> 2) * 4;
                *(uint4*)&xs[tid * 36 + c]      = make_uint4(fxh[0], fxh[1], fxh[2], fxh[3]);
                *(uint4*)&xs[tid * 36 + 16 + c] = make_uint4(fxl[0], fxl[1], fxl[2], fxl[3]);
                *(uint4*)&hs[tid * 36 + c]      = make_uint4(fhh[0], fhh[1], fhh[2], fhh[3]);
                *(uint4*)&hs[tid * 36 + 16 + c] = make_uint4(fhl[0], fhl[1], fhl[2], fhl[3]);
            }
        }
    }
    __syncwarp();   // tiles are warp-local

#define LDFRAGS(base_a, ah, al, kt)                                            \
    {                                                                          \
        uint32_t ca = (uint32_t)(((kt) * 16 + lhi * 8) * 2);                   \
        _Pragma("unroll")                                                      \
        for (int mt = 0; mt < 2; mt++) {                                       \
            uint32_t rowb = (base_a) + (uint32_t)((wpx + mt * 16 + l15) * 144);\
            ldmA((ah)[mt], rowb + ca);                                         \
            ldmA((al)[mt], rowb + ca + 64);                                    \
        }                                                                      \
    }

#define BFRAG(m, kt, nt) __ldg(&wfv[(((m) * 2 + (kt)) * 4 + (nt)) * 32 + lane])

// One matrix, one kt: 16 MMAs (2 split terms), term-major (dep distance 8),
// B fragments register-cached (4 uint2).
#define MMA_MAT(d, m, kt, ah, al)                                              \
    {                                                                          \
        uint2 b0 = BFRAG(m, kt, 0), b1 = BFRAG(m, kt, 1);                      \
        uint2 b2 = BFRAG(m, kt, 2), b3 = BFRAG(m, kt, 3);                      \
        mma16816((d)[0][0], (ah)[0], b0.x, b0.y);                              \
        mma16816((d)[1][0], (ah)[1], b0.x, b0.y);                              \
        mma16816((d)[0][1], (ah)[0], b1.x, b1.y);                              \
        mma16816((d)[1][1], (ah)[1], b1.x, b1.y);                              \
        mma16816((d)[0][2], (ah)[0], b2.x, b2.y);                              \
        mma16816((d)[1][2], (ah)[1], b2.x, b2.y);                              \
        mma16816((d)[0][3], (ah)[0], b3.x, b3.y);                              \
        mma16816((d)[1][3], (ah)[1], b3.x, b3.y);                              \
        mma16816((d)[0][0], (al)[0], b0.x, b0.y);                              \
        mma16816((d)[1][0], (al)[1], b0.x, b0.y);                              \
        mma16816((d)[0][1], (al)[0], b1.x, b1.y);                              \
        mma16816((d)[1][1], (al)[1], b1.x, b1.y);                              \
        mma16816((d)[0][2], (al)[0], b2.x, b2.y);                              \
        mma16816((d)[1][2], (al)[1], b2.x, b2.y);                              \
        mma16816((d)[0][3], (al)[0], b3.x, b3.y);                              \
        mma16816((d)[1][3], (al)[1], b3.x, b3.y);                              \
    }

    // ---- phase 1: z_pre, r_pre (64 accumulators live) ----
    float dz[2][4][4] = {}, dr[2][4][4] = {};
#pragma unroll
    for (int kt = 0; kt < 2; kt++) {
        uint32_t ah[2][4], al[2][4];
        LDFRAGS(xs_a, ah, al, kt)
        MMA_MAT(dz, 0, kt, ah, al)
        MMA_MAT(dr, 2, kt, ah, al)
        LDFRAGS(hs_a, ah, al, kt)
        MMA_MAT(dz, 1, kt, ah, al)
        MMA_MAT(dr, 3, kt, ah, al)
    }

    // z = sigmoid(z_pre + bz) kept in dz; rv = sigmoid(r_pre + br) * h -> ts
#pragma unroll
    for (int mt = 0; mt < 2; mt++)
#pragma unroll
        for (int nt = 0; nt < 4; nt++) {
            const int ch0 = nt * 8 + 2 * tig;
            const float bz0 = cBias[ch0], bz1 = cBias[ch0 + 1];
            const float br0 = cBias[32 + ch0], br1 = cBias[32 + ch0 + 1];
#pragma unroll
            for (int hf = 0; hf < 2; hf++) {
                int px = wpx + mt * 16 + g + hf * 8;
                int wb = px * 36 + nt * 4 + tig;
                float2 fh = up2(hs[wb]), fl = up2(hs[wb + 16]);
                float h0 = fh.x + fl.x;
                float h1 = fh.y + fl.y;
                dz[mt][nt][hf * 2 + 0] = sigmoidf_(dz[mt][nt][hf * 2 + 0] + bz0);
                dz[mt][nt][hf * 2 + 1] = sigmoidf_(dz[mt][nt][hf * 2 + 1] + bz1);
                float r0 = sigmoidf_(dr[mt][nt][hf * 2 + 0] + br0) * h0;
                float r1 = sigmoidf_(dr[mt][nt][hf * 2 + 1] + br1) * h1;
                uint32_t phi, plo;
                split2(r0, r1, phi, plo);
                ts[wb] = phi;  ts[wb + 16] = plo;
            }
        }
    __syncwarp();

    // ---- phase 2: dc = Wc*x + Wu*rv  (xs intact, rv in ts) ----
    float dc[2][4][4] = {};
#pragma unroll
    for (int kt = 0; kt < 2; kt++) {
        uint32_t ah[2][4], al[2][4];
        LDFRAGS(xs_a, ah, al, kt)
        MMA_MAT(dc, 4, kt, ah, al)
        LDFRAGS(ts_a, ah, al, kt)
        MMA_MAT(dc, 5, kt, ah, al)
    }
    __syncwarp();   // rv reads done before ts overwrite

    // blend: h_t = h + z*(tanh(c_pre+bc) - h) -> ts (fp16 split)
#pragma unroll
    for (int mt = 0; mt < 2; mt++)
#pragma unroll
        for (int nt = 0; nt < 4; nt++) {
            const int ch0 = nt * 8 + 2 * tig;
            const float bc0 = cBias[64 + ch0], bc1 = cBias[64 + ch0 + 1];
#pragma unroll
            for (int hf = 0; hf < 2; hf++) {
                int px = wpx + mt * 16 + g + hf * 8;
                int wb = px * 36 + nt * 4 + tig;
                float2 fh = up2(hs[wb]), fl = up2(hs[wb + 16]);
                float h0 = fh.x + fl.x;
                float h1 = fh.y + fl.y;
                float c0 = tanhf_(dc[mt][nt][hf * 2 + 0] + bc0);
                float c1 = tanhf_(dc[mt][nt][hf * 2 + 1] + bc1);
                float t0 = fmaf(dz[mt][nt][hf * 2 + 0], c0 - h0, h0);
                float t1 = fmaf(dz[mt][nt][hf * 2 + 1], c1 - h1, h1);
                uint32_t phi, plo;
                split2(t0, t1, phi, plo);
                ts[wb] = phi;  ts[wb + 16] = plo;
            }
        }
    __syncwarp();

    // coalesced h_t store: vectorized row readback
    {
        float* houtb = out + NB * 32 * HW + (b * 32) * HW + p0 + tid;
#pragma unroll
        for (int c = 0; c < 4; c++) {
            uint4 H = *(const uint4*)&ts[tid * 36 + c * 4];
            uint4 L = *(const uint4*)&ts[tid * 36 + 16 + c * 4];
            int ch0 = c * 8;
            float2 h0 = up2(H.x), l0 = up2(L.x);
            float2 h1 = up2(H.y), l1 = up2(L.y);
            float2 h2 = up2(H.z), l2 = up2(L.z);
            float2 h3 = up2(H.w), l3 = up2(L.w);
            houtb[(ch0 + 0) * HW] = h0.x + l0.x;
            houtb[(ch0 + 1) * HW] = h0.y + l0.y;
            houtb[(ch0 + 2) * HW] = h1.x + l1.x;
            houtb[(ch0 + 3) * HW] = h1.y + l1.y;
            houtb[(ch0 + 4) * HW] = h2.x + l2.x;
            houtb[(ch0 + 5) * HW] = h2.y + l2.y;
            houtb[(ch0 + 6) * HW] = h3.x + l3.x;
            houtb[(ch0 + 7) * HW] = h3.y + l3.y;
        }
    }

    // ---- phase 3: y = Wo * h_t + by  (h_t in ts) ----
    float dy[2][4][4] = {};
#pragma unroll
    for (int kt = 0; kt < 2; kt++) {
        uint32_t ah[2][4], al[2][4];
        LDFRAGS(ts_a, ah, al, kt)
        MMA_MAT(dy, 6, kt, ah, al)
    }
    __syncwarp();   // ht reads done before y overwrite

    // y + bias -> ts (fp16 split)
#pragma unroll
    for (int mt = 0; mt < 2; mt++)
#pragma unroll
        for (int nt = 0; nt < 4; nt++) {
            const int ch0 = nt * 8 + 2 * tig;
            const float by0 = cBias[96 + ch0], by1 = cBias[96 + ch0 + 1];
#pragma unroll
            for (int hf = 0; hf < 2; hf++) {
                int px = wpx + mt * 16 + g + hf * 8;
                int wb = px * 36 + nt * 4 + tig;
                uint32_t phi, plo;
                split2(dy[mt][nt][hf * 2 + 0] + by0,
                       dy[mt][nt][hf * 2 + 1] + by1, phi, plo);
                ts[wb] = phi;  ts[wb + 16] = plo;
            }
        }
    __syncwarp();

    // coalesced y store: vectorized row readback
    {
        float* youtb = out + (b * 32) * HW + p0 + tid;
#pragma unroll
        for (int c = 0; c < 4; c++) {
            uint4 H = *(const uint4*)&ts[tid * 36 + c * 4];
            uint4 L = *(const uint4*)&ts[tid * 36 + 16 + c * 4];
            int ch0 = c * 8;
            float2 h0 = up2(H.x), l0 = up2(L.x);
            float2 h1 = up2(H.y), l1 = up2(L.y);
            float2 h2 = up2(H.z), l2 = up2(L.z);
            float2 h3 = up2(H.w), l3 = up2(L.w);
            youtb[(ch0 + 0) * HW] = h0.x + l0.x;
            youtb[(ch0 + 1) * HW] = h0.y + l0.y;
            youtb[(ch0 + 2) * HW] = h1.x + l1.x;
            youtb[(ch0 + 3) * HW] = h1.y + l1.y;
            youtb[(ch0 + 4) * HW] = h2.x + l2.x;
            youtb[(ch0 + 5) * HW] = h2.y + l2.y;
            youtb[(ch0 + 6) * HW] = h3.x + l3.x;
            youtb[(ch0 + 7) * HW] = h3.y + l3.y;
        }
    }
}

extern "C" void kernel_launch(void* const* d_in, const int* in_sizes, int n_in,
                              void* d_out, int out_size) {
    const float* x    = (const float*)d_in[0];
    const float* h    = (const float*)d_in[1];
    const float* w_xz = (const float*)d_in[2];
    const float* b_xz = (const float*)d_in[3];
    const float* w_hz = (const float*)d_in[4];
    const float* b_hz = (const float*)d_in[5];
    const float* w_xr = (const float*)d_in[6];
    const float* b_xr = (const float*)d_in[7];
    const float* w_hr = (const float*)d_in[8];
    const float* b_hr = (const float*)d_in[9];
    const float* w_c  = (const float*)d_in[10];
    const float* b_c  = (const float*)d_in[11];
    const float* w_u  = (const float*)d_in[12];
    const float* b_u  = (const float*)d_in[13];
    const float* w_o  = (const float*)d_in[14];
    const float* b_o  = (const float*)d_in[15];
    float* out = (float*)d_out;

    prep_kernel<<<7, 512>>>(w_xz, w_hz, w_xr, w_hr, w_c, w_u, w_o,
                            b_xz, b_hz, b_xr, b_hr, b_c, b_u, b_o);

    void *csym = nullptr, *gsym = nullptr;
    cudaGetSymbolAddress(&csym, cBias);
    cudaGetSymbolAddress(&gsym, g_bias_stage);
    cudaMemcpyAsync(csym, gsym, sizeof(float) * 128, cudaMemcpyDeviceToDevice);

    cudaFuncSetAttribute(gru_mma_kernel,
                         cudaFuncAttributeMaxDynamicSharedMemorySize, SMEM_TOTAL);
    gru_mma_kernel<<<4096, 128, SMEM_TOTAL>>>(x, h, out);
}

// round 17
// speedup vs baseline: 1.8459x; 1.0691x over previous
#include <cuda_runtime.h>
#include <cuda_fp16.h>
#include <cstdint>

// ConvGRUCell via warp-level mma.sync (HMMA fp16, f32 accum), compute_103-safe.
// R17: x uses a SINGLE fp16 term (x feeds only pre-activations; quant error
// ~1.4e-4 adds in quadrature -> ~3e-4 total). h and ts (rv/h_t/y) keep the
// 2-term hi/lo split since they flow into the outputs. MMAs 224 -> 176/warp,
// ldmatrix 40 -> 28. xs keeps the 36-word row stride (lo half unused) so the
// proven swizzle-free layout is untouched; occupancy is register-bound at
// 4 CTAs/SM regardless of smem.

#define HW 65536        // 256*256
#define NB 8

#define TILE_BYTES 18432
#define SMEM_TOTAL (3 * TILE_BYTES)

__device__ __align__(16) uint32_t g_wfrag[3584];   // uint2 pairs {b0,b1}
__device__ float g_bias_stage[128];
__constant__ float cBias[128];   // [bz | br | bc | by]

__device__ __forceinline__ float sigmoidf_(float a) {
    a = fminf(fmaxf(a, -30.f), 30.f);
    float e = __expf(-a);
    return __fdividef(1.f, 1.f + e);
}
__device__ __forceinline__ float tanhf_(float a) {
    a = fminf(fmaxf(a, -15.f), 15.f);
    float e = __expf(-2.f * a);
    return (1.f - e) * __fdividef(1.f, 1.f + e);
}
// fp16x2 split: hi = {f16(a), f16(b)} (RN), lo = residuals in f16.
__device__ __forceinline__ void split2(float a, float b, uint32_t& hi, uint32_t& lo) {
    __half2 hp = __floats2half2_rn(a, b);
    float2 back = __half22float2(hp);
    __half2 lp = __floats2half2_rn(a - back.x, b - back.y);
    hi = *(uint32_t*)&hp;
    lo = *(uint32_t*)&lp;
}
__device__ __forceinline__ uint32_t pack1(float a, float b) {
    __half2 hp = __floats2half2_rn(a, b);
    return *(uint32_t*)&hp;
}
__device__ __forceinline__ float2 up2(uint32_t v) {
    return __half22float2(*(__half2*)&v);
}
__device__ __forceinline__ uint32_t smem_u32(const void* p) {
    uint32_t a;
    asm("{ .reg .u64 t; cvta.to.shared.u64 t, %1; cvt.u32.u64 %0, t; }"
        : "=r"(a) : "l"(p));
    return a;
}
__device__ __forceinline__ void ldmA(uint32_t a[4], uint32_t addr) {
    asm volatile("ldmatrix.sync.aligned.m8n8.x4.shared.b16 {%0,%1,%2,%3}, [%4];"
                 : "=r"(a[0]), "=r"(a[1]), "=r"(a[2]), "=r"(a[3]) : "r"(addr));
}
__device__ __forceinline__ void mma16816(float d[4], const uint32_t a[4],
                                         uint32_t b0, uint32_t b1) {
    asm volatile(
        "mma.sync.aligned.m16n8k16.row.col.f32.f16.f16.f32 "
        "{%0,%1,%2,%3}, {%4,%5,%6,%7}, {%8,%9}, {%0,%1,%2,%3};"
        : "+f"(d[0]), "+f"(d[1]), "+f"(d[2]), "+f"(d[3])
        : "r"(a[0]), "r"(a[1]), "r"(a[2]), "r"(a[3]), "r"(b0), "r"(b1));
}

// prep: fp16 B fragments, uint2 {b0,b1} per (m,kt,nt,lane).
__global__ void prep_kernel(
    const float* __restrict__ w_xz, const float* __restrict__ w_hz,
    const float* __restrict__ w_xr, const float* __restrict__ w_hr,
    const float* __restrict__ w_c,  const float* __restrict__ w_u,
    const float* __restrict__ w_o,
    const float* __restrict__ b_xz, const float* __restrict__ b_hz,
    const float* __restrict__ b_xr, const float* __restrict__ b_hr,
    const float* __restrict__ b_c,  const float* __restrict__ b_u,
    const float* __restrict__ b_o)
{
    int m = blockIdx.x;                  // 0..6
    int t = threadIdx.x;                 // 0..511
    int lane = t & 31;
    int reg  = (t >> 5) & 1;
    int nt   = (t >> 6) & 3;
    int kt   = (t >> 8) & 1;
    int g = lane >> 2, tig = lane & 3;
    const float* Wm = (m == 0) ? w_xz : (m == 1) ? w_hz : (m == 2) ? w_xr :
                      (m == 3) ? w_hr : (m == 4) ? w_c  : (m == 5) ? w_u : w_o;
    int n  = nt * 8 + g;
    int kk = kt * 16 + 2 * tig + reg * 8;
    __half2 hp = __floats2half2_rn(Wm[n * 32 + kk], Wm[n * 32 + kk + 1]);
    g_wfrag[((((m * 2 + kt) * 4 + nt) * 32) + lane) * 2 + reg] = *(uint32_t*)&hp;
    if (m == 0 && t < 32) {
        g_bias_stage[ 0 + t] = b_xz[t] + b_hz[t];
        g_bias_stage[32 + t] = b_xr[t] + b_hr[t];
        g_bias_stage[64 + t] = b_c[t]  + b_u[t];
        g_bias_stage[96 + t] = b_o[t];
    }
}

__global__ void __launch_bounds__(128, 4) gru_mma_kernel(
    const float* __restrict__ x, const float* __restrict__ h,
    float* __restrict__ out)
{
    extern __shared__ __align__(16) unsigned char dsm[];
    uint32_t* xs = (uint32_t*)dsm;                            // 36 u32 / row (hi only)
    uint32_t* hs = (uint32_t*)(dsm + TILE_BYTES);
    uint32_t* ts = (uint32_t*)(dsm + 2 * TILE_BYTES);         // rv -> ht -> y
    const uint2* __restrict__ wfv = (const uint2*)g_wfrag;    // L1-resident

    const int tid = threadIdx.x;
    const int wid = tid >> 5, lane = tid & 31;
    const int g = lane >> 2, tig = lane & 3;
    const int wpx = wid * 32;
    const int l15 = lane & 15, lhi = lane >> 4;

    const uint32_t xs_a = smem_u32(xs);
    const uint32_t hs_a = smem_u32(hs);
    const uint32_t ts_a = smem_u32(ts);

    const int gp0 = blockIdx.x * 128;   // 4096 blocks cover 524288 px
    const int b   = gp0 >> 16;
    const int p0  = gp0 & 65535;
    const float* xb = x + (b * 32) * HW + p0 + tid;
    const float* hb = h + (b * 32) * HW + p0 + tid;

    // ---- load x,h; x -> single fp16, h -> fp16 hi/lo; fill tiles ----
    {
        uint32_t fx[4], fhh[4], fhl[4];
#pragma unroll
        for (int j = 0; j < 16; j++) {
            float a0 = xb[(2 * j) * HW], a1 = xb[(2 * j + 1) * HW];
            float c0 = hb[(2 * j) * HW], c1 = hb[(2 * j + 1) * HW];
            int e = j & 3;
            fx[e] = pack1(a0, a1);
            split2(c0, c1, fhh[e], fhl[e]);
            if (e == 3) {
                int c = (j >> 2) * 4;
                *(uint4*)&xs[tid * 36 + c]      = make_uint4(fx[0], fx[1], fx[2], fx[3]);
                *(uint4*)&hs[tid * 36 + c]      = make_uint4(fhh[0], fhh[1], fhh[2], fhh[3]);
                *(uint4*)&hs[tid * 36 + 16 + c] = make_uint4(fhl[0], fhl[1], fhl[2], fhl[3]);
            }
        }
    }
    __syncwarp();   // tiles are warp-local

#define LDFRAGS(base_a, ah, al, kt)                                            \
    {                                                                          \
        uint32_t ca = (uint32_t)(((kt) * 16 + lhi * 8) * 2);                   \
        _Pragma("unroll")                                                      \
        for (int mt = 0; mt < 2; mt++) {                                       \
            uint32_t rowb = (base_a) + (uint32_t)((wpx + mt * 16 + l15) * 144);\
            ldmA((ah)[mt], rowb + ca);                                         \
            ldmA((al)[mt], rowb + ca + 64);                                    \
        }                                                                      \
    }

#define LDFRAGS1(base_a, ah, kt)                                               \
    {                                                                          \
        uint32_t ca = (uint32_t)(((kt) * 16 + lhi * 8) * 2);                   \
        _Pragma("unroll")                                                      \
        for (int mt = 0; mt < 2; mt++) {                                       \
            uint32_t rowb = (base_a) + (uint32_t)((wpx + mt * 16 + l15) * 144);\
            ldmA((ah)[mt], rowb + ca);                                         \
        }                                                                      \
    }

#define BFRAG(m, kt, nt) __ldg(&wfv[(((m) * 2 + (kt)) * 4 + (nt)) * 32 + lane])

// 2-term variant (16 MMAs), term-major (dep distance 8).
#define MMA_MAT(d, m, kt, ah, al)                                              \
    {                                                                          \
        uint2 b0 = BFRAG(m, kt, 0), b1 = BFRAG(m, kt, 1);                      \
        uint2 b2 = BFRAG(m, kt, 2), b3 = BFRAG(m, kt, 3);                      \
        mma16816((d)[0][0], (ah)[0], b0.x, b0.y);                              \
        mma16816((d)[1][0], (ah)[1], b0.x, b0.y);                              \
        mma16816((d)[0][1], (ah)[0], b1.x, b1.y);                              \
        mma16816((d)[1][1], (ah)[1], b1.x, b1.y);                              \
        mma16816((d)[0][2], (ah)[0], b2.x, b2.y);                              \
        mma16816((d)[1][2], (ah)[1], b2.x, b2.y);                              \
        mma16816((d)[0][3], (ah)[0], b3.x, b3.y);                              \
        mma16816((d)[1][3], (ah)[1], b3.x, b3.y);                              \
        mma16816((d)[0][0], (al)[0], b0.x, b0.y);                              \
        mma16816((d)[1][0], (al)[1], b0.x, b0.y);                              \
        mma16816((d)[0][1], (al)[0], b1.x, b1.y);                              \
        mma16816((d)[1][1], (al)[1], b1.x, b1.y);                              \
        mma16816((d)[0][2], (al)[0], b2.x, b2.y);                              \
        mma16816((d)[1][2], (al)[1], b2.x, b2.y);                              \
        mma16816((d)[0][3], (al)[0], b3.x, b3.y);                              \
        mma16816((d)[1][3], (al)[1], b3.x, b3.y);                              \
    }

// single-term variant (8 MMAs) for x.
#define MMA_MAT1(d, m, kt, ah)                                                 \
    {                                                                          \
        uint2 b0 = BFRAG(m, kt, 0), b1 = BFRAG(m, kt, 1);                      \
        uint2 b2 = BFRAG(m, kt, 2), b3 = BFRAG(m, kt, 3);                      \
        mma16816((d)[0][0], (ah)[0], b0.x, b0.y);                              \
        mma16816((d)[1][0], (ah)[1], b0.x, b0.y);                              \
        mma16816((d)[0][1], (ah)[0], b1.x, b1.y);                              \
        mma16816((d)[1][1], (ah)[1], b1.x, b1.y);                              \
        mma16816((d)[0][2], (ah)[0], b2.x, b2.y);                              \
        mma16816((d)[1][2], (ah)[1], b2.x, b2.y);                              \
        mma16816((d)[0][3], (ah)[0], b3.x, b3.y);                              \
        mma16816((d)[1][3], (ah)[1], b3.x, b3.y);                              \
    }

    // ---- phase 1: z_pre, r_pre ----
    float dz[2][4][4] = {}, dr[2][4][4] = {};
#pragma unroll
    for (int kt = 0; kt < 2; kt++) {
        uint32_t ah[2][4], al[2][4];
        LDFRAGS1(xs_a, ah, kt)
        MMA_MAT1(dz, 0, kt, ah)
        MMA_MAT1(dr, 2, kt, ah)
        LDFRAGS(hs_a, ah, al, kt)
        MMA_MAT(dz, 1, kt, ah, al)
        MMA_MAT(dr, 3, kt, ah, al)
    }

    // z = sigmoid(z_pre + bz) kept in dz; rv = sigmoid(r_pre + br) * h -> ts
#pragma unroll
    for (int mt = 0; mt < 2; mt++)
#pragma unroll
        for (int nt = 0; nt < 4; nt++) {
            const int ch0 = nt * 8 + 2 * tig;
            const float bz0 = cBias[ch0], bz1 = cBias[ch0 + 1];
            const float br0 = cBias[32 + ch0], br1 = cBias[32 + ch0 + 1];
#pragma unroll
            for (int hf = 0; hf < 2; hf++) {
                int px = wpx + mt * 16 + g + hf * 8;
                int wb = px * 36 + nt * 4 + tig;
                float2 fh = up2(hs[wb]), fl = up2(hs[wb + 16]);
                float h0 = fh.x + fl.x;
                float h1 = fh.y + fl.y;
                dz[mt][nt][hf * 2 + 0] = sigmoidf_(dz[mt][nt][hf * 2 + 0] + bz0);
                dz[mt][nt][hf * 2 + 1] = sigmoidf_(dz[mt][nt][hf * 2 + 1] + bz1);
                float r0 = sigmoidf_(dr[mt][nt][hf * 2 + 0] + br0) * h0;
                float r1 = sigmoidf_(dr[mt][nt][hf * 2 + 1] + br1) * h1;
                uint32_t phi, plo;
                split2(r0, r1, phi, plo);
                ts[wb] = phi;  ts[wb + 16] = plo;
            }
        }
    __syncwarp();

    // ---- phase 2: dc = Wc*x + Wu*rv ----
    float dc[2][4][4] = {};
#pragma unroll
    for (int kt = 0; kt < 2; kt++) {
        uint32_t ah[2][4], al[2][4];
        LDFRAGS1(xs_a, ah, kt)
        MMA_MAT1(dc, 4, kt, ah)
        LDFRAGS(ts_a, ah, al, kt)
        MMA_MAT(dc, 5, kt, ah, al)
    }
    __syncwarp();   // rv reads done before ts overwrite

    // blend: h_t = h + z*(tanh(c_pre+bc) - h) -> ts (fp16 split)
#pragma unroll
    for (int mt = 0; mt < 2; mt++)
#pragma unroll
        for (int nt = 0; nt < 4; nt++) {
            const int ch0 = nt * 8 + 2 * tig;
            const float bc0 = cBias[64 + ch0], bc1 = cBias[64 + ch0 + 1];
#pragma unroll
            for (int hf = 0; hf < 2; hf++) {
                int px = wpx + mt * 16 + g + hf * 8;
                int wb = px * 36 + nt * 4 + tig;
                float2 fh = up2(hs[wb]), fl = up2(hs[wb + 16]);
                float h0 = fh.x + fl.x;
                float h1 = fh.y + fl.y;
                float c0 = tanhf_(dc[mt][nt][hf * 2 + 0] + bc0);
                float c1 = tanhf_(dc[mt][nt][hf * 2 + 1] + bc1);
                float t0 = fmaf(dz[mt][nt][hf * 2 + 0], c0 - h0, h0);
                float t1 = fmaf(dz[mt][nt][hf * 2 + 1], c1 - h1, h1);
                uint32_t phi, plo;
                split2(t0, t1, phi, plo);
                ts[wb] = phi;  ts[wb + 16] = plo;
            }
        }
    __syncwarp();

    // coalesced h_t store: vectorized row readback
    {
        float* houtb = out + NB * 32 * HW + (b * 32) * HW + p0 + tid;
#pragma unroll
        for (int c = 0; c < 4; c++) {
            uint4 H = *(const uint4*)&ts[tid * 36 + c * 4];
            uint4 L = *(const uint4*)&ts[tid * 36 + 16 + c * 4];
            int ch0 = c * 8;
            float2 h0 = up2(H.x), l0 = up2(L.x);
            float2 h1 = up2(H.y), l1 = up2(L.y);
            float2 h2 = up2(H.z), l2 = up2(L.z);
            float2 h3 = up2(H.w), l3 = up2(L.w);
            houtb[(ch0 + 0) * HW] = h0.x + l0.x;
            houtb[(ch0 + 1) * HW] = h0.y + l0.y;
            houtb[(ch0 + 2) * HW] = h1.x + l1.x;
            houtb[(ch0 + 3) * HW] = h1.y + l1.y;
            houtb[(ch0 + 4) * HW] = h2.x + l2.x;
            houtb[(ch0 + 5) * HW] = h2.y + l2.y;
            houtb[(ch0 + 6) * HW] = h3.x + l3.x;
            houtb[(ch0 + 7) * HW] = h3.y + l3.y;
        }
    }

    // ---- phase 3: y = Wo * h_t + by  (h_t in ts, 2-term) ----
    float dy[2][4][4] = {};
#pragma unroll
    for (int kt = 0; kt < 2; kt++) {
        uint32_t ah[2][4], al[2][4];
        LDFRAGS(ts_a, ah, al, kt)
        MMA_MAT(dy, 6, kt, ah, al)
    }
    __syncwarp();   // ht reads done before y overwrite

    // y + bias -> ts (fp16 split)
#pragma unroll
    for (int mt = 0; mt < 2; mt++)
#pragma unroll
        for (int nt = 0; nt < 4; nt++) {
            const int ch0 = nt * 8 + 2 * tig;
            const float by0 = cBias[96 + ch0], by1 = cBias[96 + ch0 + 1];
#pragma unroll
            for (int hf = 0; hf < 2; hf++) {
                int px = wpx + mt * 16 + g + hf * 8;
                int wb = px * 36 + nt * 4 + tig;
                uint32_t phi, plo;
                split2(dy[mt][nt][hf * 2 + 0] + by0,
                       dy[mt][nt][hf * 2 + 1] + by1, phi, plo);
                ts[wb] = phi;  ts[wb + 16] = plo;
            }
        }
    __syncwarp();

    // coalesced y store: vectorized row readback
    {
        float* youtb = out + (b * 32) * HW + p0 + tid;
#pragma unroll
        for (int c = 0; c < 4; c++) {
            uint4 H = *(const uint4*)&ts[tid * 36 + c * 4];
            uint4 L = *(const uint4*)&ts[tid * 36 + 16 + c * 4];
            int ch0 = c * 8;
            float2 h0 = up2(H.x), l0 = up2(L.x);
            float2 h1 = up2(H.y), l1 = up2(L.y);
            float2 h2 = up2(H.z), l2 = up2(L.z);
            float2 h3 = up2(H.w), l3 = up2(L.w);
            youtb[(ch0 + 0) * HW] = h0.x + l0.x;
            youtb[(ch0 + 1) * HW] = h0.y + l0.y;
            youtb[(ch0 + 2) * HW] = h1.x + l1.x;
            youtb[(ch0 + 3) * HW] = h1.y + l1.y;
            youtb[(ch0 + 4) * HW] = h2.x + l2.x;
            youtb[(ch0 + 5) * HW] = h2.y + l2.y;
            youtb[(ch0 + 6) * HW] = h3.x + l3.x;
            youtb[(ch0 + 7) * HW] = h3.y + l3.y;
        }
    }
}

extern "C" void kernel_launch(void* const* d_in, const int* in_sizes, int n_in,
                              void* d_out, int out_size) {
    const float* x    = (const float*)d_in[0];
    const float* h    = (const float*)d_in[1];
    const float* w_xz = (const float*)d_in[2];
    const float* b_xz = (const float*)d_in[3];
    const float* w_hz = (const float*)d_in[4];
    const float* b_hz = (const float*)d_in[5];
    const float* w_xr = (const float*)d_in[6];
    const float* b_xr = (const float*)d_in[7];
    const float* w_hr = (const float*)d_in[8];
    const float* b_hr = (const float*)d_in[9];
    const float* w_c  = (const float*)d_in[10];
    const float* b_c  = (const float*)d_in[11];
    const float* w_u  = (const float*)d_in[12];
    const float* b_u  = (const float*)d_in[13];
    const float* w_o  = (const float*)d_in[14];
    const float* b_o  = (const float*)d_in[15];
    float* out = (float*)d_out;

    prep_kernel<<<7, 512>>>(w_xz, w_hz, w_xr, w_hr, w_c, w_u, w_o,
                            b_xz, b_hz, b_xr, b_hr, b_c, b_u, b_o);

    void *csym = nullptr, *gsym = nullptr;
    cudaGetSymbolAddress(&csym, cBias);
    cudaGetSymbolAddress(&gsym, g_bias_stage);
    cudaMemcpyAsync(csym, gsym, sizeof(float) * 128, cudaMemcpyDeviceToDevice);

    cudaFuncSetAttribute(gru_mma_kernel,
                         cudaFuncAttributeMaxDynamicSharedMemorySize, SMEM_TOTAL);
    gru_mma_kernel<<<4096, 128, SMEM_TOTAL>>>(x, h, out);
}